// round 9
// baseline (speedup 1.0000x reference)
#include <cuda_runtime.h>
#include <cuda_fp16.h>
#include <cstdint>

#define N_NODES 100000
#define N_EDGES 1600000
#define D       64
#define DH      128
#define KIN     192

#define TILE_E   64
#define N_TILES  (N_EDGES / TILE_E)   // 25000
#define EK_GRID  148
#define EK_THREADS 512                // 2 groups x 256

// ---------------- edge-kernel smem byte offsets ------------------------------
#define OFF_W1E   0          // W1e^T fp16x2 [128 rows][36 words] = 18432
#define OFF_W2    18432      // W2^T [64][68] = 17408
#define OFF_WE    35840      // We^T [64][68] = 17408
#define OFF_BI1   53248      // 512
#define OFF_BI2   53760      // 256
#define OFF_BIE   54016      // 256
#define OFF_GRP   54272
// group block: planes 24576 | HSR 64x65 words 16640 | mf 16640 | ridx 256
#define GRP_BYTES 58112
#define GOFF_HSR  24576
#define GOFF_MF   41216
#define GOFF_RIDX 57856
#define SMEM_EDGE_BYTES (OFF_GRP + 2 * GRP_BYTES)   // 170496

// ---------------- precompute-kernel smem -------------------------------------
#define POFF_WS   0          // W1s^T [128][36] = 18432
#define POFF_WR   18432      // W1r^T [128][36] = 18432
#define POFF_PL   36864      // planes 32 x 64 words = 8192
#define SMEM_PRE_BYTES 45056

// ---------------- helpers ----------------------------------------------------
__device__ __forceinline__ uint32_t packh2(float lo, float hi) {
    uint32_t d;
    asm("cvt.rn.f16x2.f32 %0, %1, %2;" : "=r"(d) : "f"(hi), "f"(lo));
    return d;
}
__device__ __forceinline__ void mma16(float* c, const uint32_t* a, const uint32_t* b) {
    asm volatile(
        "mma.sync.aligned.m16n8k16.row.col.f32.f16.f16.f32 "
        "{%0,%1,%2,%3}, {%4,%5,%6,%7}, {%8,%9}, {%0,%1,%2,%3};"
        : "+f"(c[0]), "+f"(c[1]), "+f"(c[2]), "+f"(c[3])
        : "r"(a[0]), "r"(a[1]), "r"(a[2]), "r"(a[3]), "r"(b[0]), "r"(b[1]));
}

// ---------------- scratch ----------------------------------------------------
__device__ float  g_agg[(size_t)N_NODES * D];
__device__ __half g_H1[(size_t)N_NODES * DH];   // h @ W1[64:128]
__device__ __half g_H2[(size_t)N_NODES * DH];   // h @ W1[128:192]

__global__ void zero_agg_kernel() {
    size_t i = (size_t)blockIdx.x * blockDim.x + threadIdx.x;
    size_t n4 = (size_t)N_NODES * D / 4;
    if (i < n4) ((float4*)g_agg)[i] = make_float4(0.f, 0.f, 0.f, 0.f);
}

// ---------------- precompute: H1 = h@W1s, H2 = h@W1r (fp16 mma) --------------
__global__ void __launch_bounds__(256)
pre_kernel(const float* __restrict__ h, const float* __restrict__ W1)
{
    extern __shared__ char smc[];
    uint32_t* WSw = (uint32_t*)(smc + POFF_WS);
    uint32_t* WRw = (uint32_t*)(smc + POFF_WR);
    uint32_t* PW  = (uint32_t*)(smc + POFF_PL);

    const int tid  = threadIdx.x;
    const int w    = tid >> 5;
    const int lane = tid & 31;
    const int g    = lane >> 2;
    const int tig  = lane & 3;
    const int swz  = tig << 3;

    // stage W1s (rows 64..127) and W1r (rows 128..191) in fragment order
    for (int i = tid; i < DH * 32; i += 256) {
        int c = i >> 5, k2 = i & 31;
        WSw[c * 36 + k2] = packh2(W1[(64 + 2 * k2) * DH + c],
                                  W1[(64 + 2 * k2 + 1) * DH + c]);
        WRw[c * 36 + k2] = packh2(W1[(128 + 2 * k2) * DH + c],
                                  W1[(128 + 2 * k2 + 1) * DH + c]);
    }
    __syncthreads();

    const int base = blockIdx.x * 64;

    // gather 64 node rows (contiguous) -> planes p0..31
    {
        const int nl = tid & 63;
        const int p4 = tid >> 2 >> 4;   // tid>>6
        const int node = base + nl;
        #pragma unroll
        for (int q = 0; q < 4; q++) {
            float4 v = (node < N_NODES)
                ? ((const float4*)(h + (size_t)node * D))[p4 * 4 + q]
                : make_float4(0.f, 0.f, 0.f, 0.f);
            int p = p4 * 8 + q * 2;
            PW[p * 64 + (nl ^ ((p & 3) << 3))]             = packh2(v.x, v.y);
            PW[(p + 1) * 64 + (nl ^ (((p + 1) & 3) << 3))] = packh2(v.z, v.w);
        }
    }
    __syncthreads();

    const int c0 = (w & 3) * 32;
    const int n0 = (w >> 2) * 32;

    float accS[2][4][4], accR[2][4][4];
    #pragma unroll
    for (int mt = 0; mt < 2; mt++)
        #pragma unroll
        for (int nt = 0; nt < 4; nt++)
            #pragma unroll
            for (int q = 0; q < 4; q++) { accS[mt][nt][q] = 0.f; accR[mt][nt][q] = 0.f; }

    #pragma unroll
    for (int kt = 0; kt < 4; kt++) {
        const int k8 = kt * 8;
        uint32_t as[2][4], ar[2][4];
        #pragma unroll
        for (int mt = 0; mt < 2; mt++) {
            int r = c0 + 16 * mt + g;
            as[mt][0] = WSw[r * 36 + k8 + tig];
            as[mt][1] = WSw[(r + 8) * 36 + k8 + tig];
            as[mt][2] = WSw[r * 36 + k8 + tig + 4];
            as[mt][3] = WSw[(r + 8) * 36 + k8 + tig + 4];
            ar[mt][0] = WRw[r * 36 + k8 + tig];
            ar[mt][1] = WRw[(r + 8) * 36 + k8 + tig];
            ar[mt][2] = WRw[r * 36 + k8 + tig + 4];
            ar[mt][3] = WRw[(r + 8) * 36 + k8 + tig + 4];
        }
        uint32_t bv[4][2];
        const int p0 = k8 + tig;
        #pragma unroll
        for (int nt = 0; nt < 4; nt++) {
            int es = (n0 + nt * 8 + g) ^ swz;
            bv[nt][0] = PW[p0 * 64 + es];
            bv[nt][1] = PW[(p0 + 4) * 64 + es];
        }
        #pragma unroll
        for (int mt = 0; mt < 2; mt++)
            #pragma unroll
            for (int nt = 0; nt < 4; nt++) {
                mma16(accS[mt][nt], as[mt], bv[nt]);
                mma16(accR[mt][nt], ar[mt], bv[nt]);
            }
    }

    // store fp16 results
    #pragma unroll
    for (int mt = 0; mt < 2; mt++)
        #pragma unroll
        for (int nt = 0; nt < 4; nt++) {
            int cA = c0 + 16 * mt + g;
            int nA = n0 + 8 * nt + 2 * tig;
            int d0 = base + nA, d1 = base + nA + 1;
            if (d0 < N_NODES) {
                g_H1[(size_t)d0 * DH + cA]     = __float2half_rn(accS[mt][nt][0]);
                g_H1[(size_t)d0 * DH + cA + 8] = __float2half_rn(accS[mt][nt][2]);
                g_H2[(size_t)d0 * DH + cA]     = __float2half_rn(accR[mt][nt][0]);
                g_H2[(size_t)d0 * DH + cA + 8] = __float2half_rn(accR[mt][nt][2]);
            }
            if (d1 < N_NODES) {
                g_H1[(size_t)d1 * DH + cA]     = __float2half_rn(accS[mt][nt][1]);
                g_H1[(size_t)d1 * DH + cA + 8] = __float2half_rn(accS[mt][nt][3]);
                g_H2[(size_t)d1 * DH + cA]     = __float2half_rn(accR[mt][nt][1]);
                g_H2[(size_t)d1 * DH + cA + 8] = __float2half_rn(accR[mt][nt][3]);
            }
        }
}

// ---------------- fused edge kernel (fp16 mma, 2 tile-groups/CTA) ------------
__global__ void __launch_bounds__(EK_THREADS, 1)
edge_kernel(const float* __restrict__ h, const float* __restrict__ e,
            const int* __restrict__ senders, const int* __restrict__ receivers,
            const float* __restrict__ W1, const float* __restrict__ b1,
            const float* __restrict__ W2, const float* __restrict__ b2,
            const float* __restrict__ We, const float* __restrict__ be,
            float* __restrict__ out_e)
{
    extern __shared__ char smc[];
    uint32_t* W1w = (uint32_t*)(smc + OFF_W1E);
    uint32_t* W2w = (uint32_t*)(smc + OFF_W2);
    uint32_t* WEw = (uint32_t*)(smc + OFF_WE);
    float* bi1 = (float*)(smc + OFF_BI1);
    float* bi2 = (float*)(smc + OFF_BI2);
    float* bie = (float*)(smc + OFF_BIE);

    const int tid = threadIdx.x;

    // ---- stage shared weights + biases --------------------------------------
    for (int i = tid; i < DH * 32; i += EK_THREADS) {        // W1e: k 0..63
        int c = i >> 5, k2 = i & 31;
        W1w[c * 36 + k2] = packh2(W1[(2 * k2) * DH + c], W1[(2 * k2 + 1) * DH + c]);
    }
    for (int i = tid; i < D * (DH / 2); i += EK_THREADS) {
        int c = i >> 6, k2 = i & 63;
        W2w[c * 68 + k2] = packh2(W2[(2 * k2) * D + c], W2[(2 * k2 + 1) * D + c]);
        WEw[c * 68 + k2] = packh2(We[(2 * k2) * D + c], We[(2 * k2 + 1) * D + c]);
    }
    if (tid < DH) bi1[tid] = b1[tid];
    if (tid < D)  bi2[tid] = b2[tid];
    else if (tid < 2 * D) bie[tid - D] = be[tid - D];
    __syncthreads();

    // ---- group-local state ---------------------------------------------------
    const int gi   = tid >> 8;
    const int lt   = tid & 255;
    const int w    = lt >> 5;
    const int lane = lt & 31;
    const int g    = lane >> 2;
    const int tig  = lane & 3;
    const int swz  = tig << 3;

    char* gbase = smc + OFF_GRP + gi * GRP_BYTES;
    uint32_t* PW   = (uint32_t*)gbase;
    __half*   PHh  = (__half*)gbase;
    uint32_t* HSRw = (uint32_t*)(gbase + GOFF_HSR);
    const __half* HSRh = (const __half*)(gbase + GOFF_HSR);
    float*    mf   = (float*)(gbase + GOFF_MF);
    int*      ridx = (int*)(gbase + GOFF_RIDX);

    const int c0w1 = (w & 3) * 32;
    const int e0w1 = (w >> 2) * 32;
    const int wl   = w & 3;
    const int c0w2 = (wl & 1) * 32;
    const int e0w2 = (wl >> 1) * 32;
    const int barid = gi + 1;

    #define BARG() asm volatile("bar.sync %0, 256;" :: "r"(barid) : "memory")

    for (int tile = blockIdx.x * 2 + gi; tile < N_TILES; tile += 2 * gridDim.x) {
        const int base = tile * TILE_E;
        BARG();   // S0

        // ====== gather: e -> planes p0..31;  H1[s]+H2[r] -> HSR (fp16) =======
        {
            const int el = lt & 63;
            const int p4 = lt >> 6;
            const int sI = senders[base + el];
            const int rI = receivers[base + el];
            if (p4 == 0) ridx[el] = rI;
            const float4* ep = (const float4*)(e + (size_t)(base + el) * D) + p4 * 4;
            #pragma unroll
            for (int q = 0; q < 4; q++) {
                float4 v = ep[q];
                int p = p4 * 8 + q * 2;
                PW[p * 64 + (el ^ ((p & 3) << 3))]             = packh2(v.x, v.y);
                PW[(p + 1) * 64 + (el ^ (((p + 1) & 3) << 3))] = packh2(v.z, v.w);
            }
            const uint4* h1p = (const uint4*)(g_H1 + (size_t)sI * DH) + p4 * 4;
            const uint4* h2p = (const uint4*)(g_H2 + (size_t)rI * DH) + p4 * 4;
            uint32_t* dst = HSRw + el * 65 + p4 * 16;
            #pragma unroll
            for (int q = 0; q < 4; q++) {
                uint4 a = h1p[q], b = h2p[q];
                __half2 s0 = __hadd2(*(__half2*)&a.x, *(__half2*)&b.x);
                __half2 s1 = __hadd2(*(__half2*)&a.y, *(__half2*)&b.y);
                __half2 s2 = __hadd2(*(__half2*)&a.z, *(__half2*)&b.z);
                __half2 s3 = __hadd2(*(__half2*)&a.w, *(__half2*)&b.w);
                dst[q * 4 + 0] = *(uint32_t*)&s0;
                dst[q * 4 + 1] = *(uint32_t*)&s1;
                dst[q * 4 + 2] = *(uint32_t*)&s2;
                dst[q * 4 + 3] = *(uint32_t*)&s3;
            }
        }
        BARG();   // S1

        // ====== GEMM1': acc init = HSR + b1; += e @ W1e (K=64) ===============
        float acc1[2][4][4];
        #pragma unroll
        for (int mt = 0; mt < 2; mt++)
            #pragma unroll
            for (int nt = 0; nt < 4; nt++) {
                int cA = c0w1 + 16 * mt + g;
                int eA = e0w1 + 8 * nt + 2 * tig;
                acc1[mt][nt][0] = __half2float(HSRh[eA * 130 + cA])           + bi1[cA];
                acc1[mt][nt][1] = __half2float(HSRh[(eA + 1) * 130 + cA])     + bi1[cA];
                acc1[mt][nt][2] = __half2float(HSRh[eA * 130 + cA + 8])       + bi1[cA + 8];
                acc1[mt][nt][3] = __half2float(HSRh[(eA + 1) * 130 + cA + 8]) + bi1[cA + 8];
            }

        #pragma unroll
        for (int kt = 0; kt < 4; kt++) {
            const int k8 = kt * 8;
            uint32_t av[2][4];
            #pragma unroll
            for (int mt = 0; mt < 2; mt++) {
                int r = c0w1 + 16 * mt + g;
                av[mt][0] = W1w[r * 36 + k8 + tig];
                av[mt][1] = W1w[(r + 8) * 36 + k8 + tig];
                av[mt][2] = W1w[r * 36 + k8 + tig + 4];
                av[mt][3] = W1w[(r + 8) * 36 + k8 + tig + 4];
            }
            uint32_t bv[4][2];
            const int p0 = k8 + tig;
            #pragma unroll
            for (int nt = 0; nt < 4; nt++) {
                int es = (e0w1 + nt * 8 + g) ^ swz;
                bv[nt][0] = PW[p0 * 64 + es];
                bv[nt][1] = PW[(p0 + 4) * 64 + es];
            }
            #pragma unroll
            for (int mt = 0; mt < 2; mt++)
                #pragma unroll
                for (int nt = 0; nt < 4; nt++)
                    mma16(acc1[mt][nt], av[mt], bv[nt]);
        }
        BARG();   // S2

        // ===== epilogue1: hid = relu(acc) -> planes p 32..95 (fp16) ==========
        #pragma unroll
        for (int mt = 0; mt < 2; mt++)
            #pragma unroll
            for (int nt = 0; nt < 4; nt++) {
                int cA = c0w1 + 16 * mt + g;
                int eA = e0w1 + 8 * nt + 2 * tig;
                float v0 = fmaxf(acc1[mt][nt][0], 0.f);
                float v1 = fmaxf(acc1[mt][nt][1], 0.f);
                float v2 = fmaxf(acc1[mt][nt][2], 0.f);
                float v3 = fmaxf(acc1[mt][nt][3], 0.f);
                int pA = 32 + (cA >> 1);
                int sub = cA & 1;
                int sw0 = (pA & 3) << 3;
                int esA = eA ^ sw0, esB = (eA + 1) ^ sw0;
                PHh[2 * (pA * 64 + esA) + sub]       = __float2half_rn(v0);
                PHh[2 * (pA * 64 + esB) + sub]       = __float2half_rn(v1);
                PHh[2 * ((pA + 4) * 64 + esA) + sub] = __float2half_rn(v2);
                PHh[2 * ((pA + 4) * 64 + esB) + sub] = __float2half_rn(v3);
            }
        BARG();   // S3

        // ===== warps0-3: GEMM2 (m = hid @ W2) | warps4-7: GEMM3a (e-part) ====
        float acc2[2][4][4];
        #pragma unroll
        for (int mt = 0; mt < 2; mt++)
            #pragma unroll
            for (int nt = 0; nt < 4; nt++)
                #pragma unroll
                for (int q = 0; q < 4; q++) acc2[mt][nt][q] = 0.f;

        if (w < 4) {
            #pragma unroll 2
            for (int kt = 0; kt < 8; kt++) {
                const int k8 = kt * 8;
                uint32_t av[2][4];
                #pragma unroll
                for (int mt = 0; mt < 2; mt++) {
                    int r = c0w2 + 16 * mt + g;
                    av[mt][0] = W2w[r * 68 + k8 + tig];
                    av[mt][1] = W2w[(r + 8) * 68 + k8 + tig];
                    av[mt][2] = W2w[r * 68 + k8 + tig + 4];
                    av[mt][3] = W2w[(r + 8) * 68 + k8 + tig + 4];
                }
                uint32_t bv[4][2];
                const int p0 = 32 + k8 + tig;
                #pragma unroll
                for (int nt = 0; nt < 4; nt++) {
                    int es = (e0w2 + nt * 8 + g) ^ swz;
                    bv[nt][0] = PW[p0 * 64 + es];
                    bv[nt][1] = PW[(p0 + 4) * 64 + es];
                }
                #pragma unroll
                for (int mt = 0; mt < 2; mt++)
                    #pragma unroll
                    for (int nt = 0; nt < 4; nt++)
                        mma16(acc2[mt][nt], av[mt], bv[nt]);
            }
        } else {
            #pragma unroll 2
            for (int kt = 0; kt < 4; kt++) {
                const int k8 = kt * 8;
                uint32_t av[2][4];
                #pragma unroll
                for (int mt = 0; mt < 2; mt++) {
                    int r = c0w2 + 16 * mt + g;
                    av[mt][0] = WEw[r * 68 + k8 + tig];
                    av[mt][1] = WEw[(r + 8) * 68 + k8 + tig];
                    av[mt][2] = WEw[r * 68 + k8 + tig + 4];
                    av[mt][3] = WEw[(r + 8) * 68 + k8 + tig + 4];
                }
                uint32_t bv[4][2];
                const int p0 = k8 + tig;
                #pragma unroll
                for (int nt = 0; nt < 4; nt++) {
                    int es = (e0w2 + nt * 8 + g) ^ swz;
                    bv[nt][0] = PW[p0 * 64 + es];
                    bv[nt][1] = PW[(p0 + 4) * 64 + es];
                }
                #pragma unroll
                for (int mt = 0; mt < 2; mt++)
                    #pragma unroll
                    for (int nt = 0; nt < 4; nt++)
                        mma16(acc2[mt][nt], av[mt], bv[nt]);
            }
        }
        BARG();   // S4

        // ===== epilogue2 (w0-3): m -> planes p 32..63 (fp16) + mf (fp32) =====
        if (w < 4) {
            #pragma unroll
            for (int mt = 0; mt < 2; mt++)
                #pragma unroll
                for (int nt = 0; nt < 4; nt++) {
                    int cA = c0w2 + 16 * mt + g;
                    int eA = e0w2 + 8 * nt + 2 * tig;
                    float v0 = acc2[mt][nt][0] + bi2[cA];
                    float v1 = acc2[mt][nt][1] + bi2[cA];
                    float v2 = acc2[mt][nt][2] + bi2[cA + 8];
                    float v3 = acc2[mt][nt][3] + bi2[cA + 8];
                    int pA = 32 + (cA >> 1);
                    int sub = cA & 1;
                    int sw0 = (pA & 3) << 3;
                    int esA = eA ^ sw0, esB = (eA + 1) ^ sw0;
                    PHh[2 * (pA * 64 + esA) + sub]       = __float2half_rn(v0);
                    PHh[2 * (pA * 64 + esB) + sub]       = __float2half_rn(v1);
                    PHh[2 * ((pA + 4) * 64 + esA) + sub] = __float2half_rn(v2);
                    PHh[2 * ((pA + 4) * 64 + esB) + sub] = __float2half_rn(v3);
                    mf[eA * 65 + cA]           = v0;
                    mf[(eA + 1) * 65 + cA]     = v1;
                    mf[eA * 65 + cA + 8]       = v2;
                    mf[(eA + 1) * 65 + cA + 8] = v3;
                }
        }
        BARG();   // S5

        if (w >= 4) {
            // ===== GEMM3b: += m @ We[64:128]  (m at p 32..63) ================
            #pragma unroll 2
            for (int kt = 4; kt < 8; kt++) {
                const int k8 = kt * 8;
                uint32_t av[2][4];
                #pragma unroll
                for (int mt = 0; mt < 2; mt++) {
                    int r = c0w2 + 16 * mt + g;
                    av[mt][0] = WEw[r * 68 + k8 + tig];
                    av[mt][1] = WEw[(r + 8) * 68 + k8 + tig];
                    av[mt][2] = WEw[r * 68 + k8 + tig + 4];
                    av[mt][3] = WEw[(r + 8) * 68 + k8 + tig + 4];
                }
                uint32_t bv[4][2];
                const int p0 = k8 + tig;
                #pragma unroll
                for (int nt = 0; nt < 4; nt++) {
                    int es = (e0w2 + nt * 8 + g) ^ swz;
                    bv[nt][0] = PW[p0 * 64 + es];
                    bv[nt][1] = PW[(p0 + 4) * 64 + es];
                }
                #pragma unroll
                for (int mt = 0; mt < 2; mt++)
                    #pragma unroll
                    for (int nt = 0; nt < 4; nt++)
                        mma16(acc2[mt][nt], av[mt], bv[nt]);
            }
            // ===== epilogue3: e_new = relu(acc+be) -> gmem ===================
            #pragma unroll
            for (int mt = 0; mt < 2; mt++)
                #pragma unroll
                for (int nt = 0; nt < 4; nt++) {
                    int cA = c0w2 + 16 * mt + g;
                    int eA = e0w2 + 8 * nt + 2 * tig;
                    float* d0 = out_e + (size_t)(base + eA) * D;
                    float* d1 = out_e + (size_t)(base + eA + 1) * D;
                    d0[cA]     = fmaxf(acc2[mt][nt][0] + bie[cA], 0.f);
                    d1[cA]     = fmaxf(acc2[mt][nt][1] + bie[cA], 0.f);
                    d0[cA + 8] = fmaxf(acc2[mt][nt][2] + bie[cA + 8], 0.f);
                    d1[cA + 8] = fmaxf(acc2[mt][nt][3] + bie[cA + 8], 0.f);
                }
        } else {
            // ===== scatter: atomicAdd m (fp32) into g_agg ====================
            const int el = lt & 63;
            const int hf = lt >> 6;
            const int r  = ridx[el];
            const float* mrow = mf + el * 65 + hf * 32;
            float* dstp = g_agg + (size_t)r * D + hf * 32;
            #pragma unroll 8
            for (int c = 0; c < 32; c++) atomicAdd(dstp + c, mrow[c]);
        }
    }
    #undef BARG
}

// ---------------- node kernel: h_new = relu([h | agg] @ W_node + b) ----------
#define NT    32
#define NPAD  36
#define NOFF_W 0
#define NOFF_B (NOFF_W + DH * D)
#define NOFF_X (NOFF_B + D)
#define SMEM_NODE_FLOATS (NOFF_X + DH * NPAD)
#define SMEM_NODE_BYTES  (SMEM_NODE_FLOATS * 4)

__global__ void __launch_bounds__(128)
node_kernel(const float* __restrict__ h,
            const float* __restrict__ Wn, const float* __restrict__ bn,
            float* __restrict__ out_h)
{
    extern __shared__ float sm[];
    const int tid = threadIdx.x;

    for (int i = tid; i < DH * D / 4; i += 128)
        ((float4*)(sm + NOFF_W))[i] = ((const float4*)Wn)[i];
    if (tid < D) sm[NOFF_B + tid] = bn[tid];
    __syncthreads();

    const int nl   = tid >> 2;
    const int part = tid & 3;
    const int ng   = tid >> 4;
    const int cgc  = tid & 15;

    const int n_tiles = N_NODES / NT;
    for (int tile = blockIdx.x; tile < n_tiles; tile += gridDim.x) {
        const int base = tile * NT;
        {
            const float4* hp = (const float4*)(h + (size_t)(base + nl) * D) + part * 4;
            const float4* ap = (const float4*)(g_agg + (size_t)(base + nl) * D) + part * 4;
            #pragma unroll
            for (int q = 0; q < 4; q++) {
                float4 v = hp[q];
                int k0 = part * 16 + q * 4;
                sm[NOFF_X + (k0 + 0) * NPAD + nl] = v.x;
                sm[NOFF_X + (k0 + 1) * NPAD + nl] = v.y;
                sm[NOFF_X + (k0 + 2) * NPAD + nl] = v.z;
                sm[NOFF_X + (k0 + 3) * NPAD + nl] = v.w;
            }
            #pragma unroll
            for (int q = 0; q < 4; q++) {
                float4 v = ap[q];
                int k0 = 64 + part * 16 + q * 4;
                sm[NOFF_X + (k0 + 0) * NPAD + nl] = v.x;
                sm[NOFF_X + (k0 + 1) * NPAD + nl] = v.y;
                sm[NOFF_X + (k0 + 2) * NPAD + nl] = v.z;
                sm[NOFF_X + (k0 + 3) * NPAD + nl] = v.w;
            }
        }
        __syncthreads();

        float acc[4][4];
        #pragma unroll
        for (int i = 0; i < 4; i++)
            #pragma unroll
            for (int j = 0; j < 4; j++) acc[i][j] = 0.f;

        const float* Xb = sm + NOFF_X + ng * 4;
        const float* Wb = sm + NOFF_W + cgc * 4;
        #pragma unroll 4
        for (int k = 0; k < DH; k++) {
            float4 a = *(const float4*)(Xb + k * NPAD);
            float4 wv4 = *(const float4*)(Wb + k * D);
            float av[4] = {a.x, a.y, a.z, a.w};
            float wv[4] = {wv4.x, wv4.y, wv4.z, wv4.w};
            #pragma unroll
            for (int i = 0; i < 4; i++)
                #pragma unroll
                for (int j = 0; j < 4; j++)
                    acc[i][j] = fmaf(av[i], wv[j], acc[i][j]);
        }
        float bb[4];
        #pragma unroll
        for (int j = 0; j < 4; j++) bb[j] = sm[NOFF_B + cgc * 4 + j];
        #pragma unroll
        for (int i = 0; i < 4; i++) {
            float4 v;
            v.x = fmaxf(acc[i][0] + bb[0], 0.f);
            v.y = fmaxf(acc[i][1] + bb[1], 0.f);
            v.z = fmaxf(acc[i][2] + bb[2], 0.f);
            v.w = fmaxf(acc[i][3] + bb[3], 0.f);
            *(float4*)(out_h + (size_t)(base + ng * 4 + i) * D + cgc * 4) = v;
        }
        __syncthreads();
    }
}

// ---------------- launch -----------------------------------------------------
extern "C" void kernel_launch(void* const* d_in, const int* in_sizes, int n_in,
                              void* d_out, int out_size)
{
    const float* h        = (const float*)d_in[0];
    const float* e        = (const float*)d_in[1];
    const int*   senders  = (const int*)d_in[2];
    const int*   receivers= (const int*)d_in[3];
    const float* W1       = (const float*)d_in[4];
    const float* b1       = (const float*)d_in[5];
    const float* W2       = (const float*)d_in[6];
    const float* b2       = (const float*)d_in[7];
    const float* Wn       = (const float*)d_in[8];
    const float* bn       = (const float*)d_in[9];
    const float* We       = (const float*)d_in[10];
    const float* be       = (const float*)d_in[11];

    float* out_h = (float*)d_out;
    float* out_e = out_h + (size_t)N_NODES * D;

    cudaFuncSetAttribute(edge_kernel, cudaFuncAttributeMaxDynamicSharedMemorySize,
                         SMEM_EDGE_BYTES);
    cudaFuncSetAttribute(node_kernel, cudaFuncAttributeMaxDynamicSharedMemorySize,
                         SMEM_NODE_BYTES);

    zero_agg_kernel<<<(N_NODES * D / 4 + 255) / 256, 256>>>();
    pre_kernel<<<(N_NODES + 63) / 64, 256, SMEM_PRE_BYTES>>>(h, W1);
    edge_kernel<<<EK_GRID, EK_THREADS, SMEM_EDGE_BYTES>>>(
        h, e, senders, receivers, W1, b1, W2, b2, We, be, out_e);
    node_kernel<<<1480, 128, SMEM_NODE_BYTES>>>(h, Wn, bn, out_h);
}

// round 10
// speedup vs baseline: 1.0303x; 1.0303x over previous
#include <cuda_runtime.h>
#include <cuda_fp16.h>
#include <cstdint>

#define N_NODES 100000
#define N_EDGES 1600000
#define D       64
#define DH      128
#define KIN     192

#define TILE_E   64
#define N_TILES  (N_EDGES / TILE_E)   // 25000
#define EK_GRID  148
#define EK_THREADS 512                // 2 groups x 256

// ---------------- edge-kernel smem byte offsets ------------------------------
#define OFF_W1E   0          // W1e^T fp16 [128 rows][36 words] = 18432
#define OFF_W2    18432      // W2^T [64 rows][68 words] = 17408
#define OFF_WE    35840      // We^T [64 rows][68 words] = 17408
#define OFF_BI1H  53248      // b1 as half2 [64 words] = 256
#define OFF_BI2   53504      // 256
#define OFF_BIE   53760      // 256
#define OFF_GRP   54016
// group block: X 64x100 words 25600 | HSR 64x68 words 17408 | mf 17408 | ridx 256
#define GRP_BYTES 60672
#define GOFF_HSR  25600
#define GOFF_MF   43008
#define GOFF_RIDX 60416
#define SMEM_EDGE_BYTES (OFF_GRP + 2 * GRP_BYTES)   // 175360

#define XSTRW 100            // X row stride in words
#define HSTRW 68             // HSR/mf row stride in words

// ---------------- precompute-kernel smem -------------------------------------
#define POFF_WS   0
#define POFF_WR   18432
#define POFF_PL   36864
#define SMEM_PRE_BYTES 45056

// ---------------- helpers ----------------------------------------------------
__device__ __forceinline__ uint32_t packh2(float lo, float hi) {
    uint32_t d;
    asm("cvt.rn.f16x2.f32 %0, %1, %2;" : "=r"(d) : "f"(hi), "f"(lo));
    return d;
}
__device__ __forceinline__ void mma16(float* c, const uint32_t* a, const uint32_t* b) {
    asm volatile(
        "mma.sync.aligned.m16n8k16.row.col.f32.f16.f16.f32 "
        "{%0,%1,%2,%3}, {%4,%5,%6,%7}, {%8,%9}, {%0,%1,%2,%3};"
        : "+f"(c[0]), "+f"(c[1]), "+f"(c[2]), "+f"(c[3])
        : "r"(a[0]), "r"(a[1]), "r"(a[2]), "r"(a[3]), "r"(b[0]), "r"(b[1]));
}
__device__ __forceinline__ void ldsm4(uint32_t* r, uint32_t saddr) {
    asm volatile("ldmatrix.sync.aligned.m8n8.x4.shared.b16 {%0,%1,%2,%3}, [%4];"
        : "=r"(r[0]), "=r"(r[1]), "=r"(r[2]), "=r"(r[3]) : "r"(saddr));
}

// ---------------- scratch ----------------------------------------------------
__device__ float  g_agg[(size_t)N_NODES * D];
__device__ __half g_H1[(size_t)N_NODES * DH];
__device__ __half g_H2[(size_t)N_NODES * DH];

__global__ void zero_agg_kernel() {
    size_t i = (size_t)blockIdx.x * blockDim.x + threadIdx.x;
    size_t n4 = (size_t)N_NODES * D / 4;
    if (i < n4) ((float4*)g_agg)[i] = make_float4(0.f, 0.f, 0.f, 0.f);
}

// ---------------- precompute: H1 = h@W1s, H2 = h@W1r -------------------------
__global__ void __launch_bounds__(256)
pre_kernel(const float* __restrict__ h, const float* __restrict__ W1)
{
    extern __shared__ char smc[];
    uint32_t* WSw = (uint32_t*)(smc + POFF_WS);
    uint32_t* WRw = (uint32_t*)(smc + POFF_WR);
    uint32_t* PW  = (uint32_t*)(smc + POFF_PL);

    const int tid  = threadIdx.x;
    const int w    = tid >> 5;
    const int lane = tid & 31;
    const int g    = lane >> 2;
    const int tig  = lane & 3;
    const int swz  = tig << 3;

    for (int i = tid; i < DH * 32; i += 256) {
        int c = i >> 5, k2 = i & 31;
        WSw[c * 36 + k2] = packh2(W1[(64 + 2 * k2) * DH + c],
                                  W1[(64 + 2 * k2 + 1) * DH + c]);
        WRw[c * 36 + k2] = packh2(W1[(128 + 2 * k2) * DH + c],
                                  W1[(128 + 2 * k2 + 1) * DH + c]);
    }
    __syncthreads();

    const int base = blockIdx.x * 64;
    {
        const int nl = tid & 63;
        const int p4 = tid >> 6;
        const int node = base + nl;
        #pragma unroll
        for (int q = 0; q < 4; q++) {
            float4 v = (node < N_NODES)
                ? ((const float4*)(h + (size_t)node * D))[p4 * 4 + q]
                : make_float4(0.f, 0.f, 0.f, 0.f);
            int p = p4 * 8 + q * 2;
            PW[p * 64 + (nl ^ ((p & 3) << 3))]             = packh2(v.x, v.y);
            PW[(p + 1) * 64 + (nl ^ (((p + 1) & 3) << 3))] = packh2(v.z, v.w);
        }
    }
    __syncthreads();

    const int c0 = (w & 3) * 32;
    const int n0 = (w >> 2) * 32;

    float accS[2][4][4], accR[2][4][4];
    #pragma unroll
    for (int mt = 0; mt < 2; mt++)
        #pragma unroll
        for (int nt = 0; nt < 4; nt++)
            #pragma unroll
            for (int q = 0; q < 4; q++) { accS[mt][nt][q] = 0.f; accR[mt][nt][q] = 0.f; }

    #pragma unroll
    for (int kt = 0; kt < 4; kt++) {
        const int k8 = kt * 8;
        uint32_t as[2][4], ar[2][4];
        #pragma unroll
        for (int mt = 0; mt < 2; mt++) {
            int r = c0 + 16 * mt + g;
            as[mt][0] = WSw[r * 36 + k8 + tig];
            as[mt][1] = WSw[(r + 8) * 36 + k8 + tig];
            as[mt][2] = WSw[r * 36 + k8 + tig + 4];
            as[mt][3] = WSw[(r + 8) * 36 + k8 + tig + 4];
            ar[mt][0] = WRw[r * 36 + k8 + tig];
            ar[mt][1] = WRw[(r + 8) * 36 + k8 + tig];
            ar[mt][2] = WRw[r * 36 + k8 + tig + 4];
            ar[mt][3] = WRw[(r + 8) * 36 + k8 + tig + 4];
        }
        uint32_t bv[4][2];
        const int p0 = k8 + tig;
        #pragma unroll
        for (int nt = 0; nt < 4; nt++) {
            int es = (n0 + nt * 8 + g) ^ swz;
            bv[nt][0] = PW[p0 * 64 + es];
            bv[nt][1] = PW[(p0 + 4) * 64 + es];
        }
        #pragma unroll
        for (int mt = 0; mt < 2; mt++)
            #pragma unroll
            for (int nt = 0; nt < 4; nt++) {
                mma16(accS[mt][nt], as[mt], bv[nt]);
                mma16(accR[mt][nt], ar[mt], bv[nt]);
            }
    }

    #pragma unroll
    for (int mt = 0; mt < 2; mt++)
        #pragma unroll
        for (int nt = 0; nt < 4; nt++) {
            int cA = c0 + 16 * mt + g;
            int nA = n0 + 8 * nt + 2 * tig;
            int d0 = base + nA, d1 = base + nA + 1;
            if (d0 < N_NODES) {
                g_H1[(size_t)d0 * DH + cA]     = __float2half_rn(accS[mt][nt][0]);
                g_H1[(size_t)d0 * DH + cA + 8] = __float2half_rn(accS[mt][nt][2]);
                g_H2[(size_t)d0 * DH + cA]     = __float2half_rn(accR[mt][nt][0]);
                g_H2[(size_t)d0 * DH + cA + 8] = __float2half_rn(accR[mt][nt][2]);
            }
            if (d1 < N_NODES) {
                g_H1[(size_t)d1 * DH + cA]     = __float2half_rn(accS[mt][nt][1]);
                g_H1[(size_t)d1 * DH + cA + 8] = __float2half_rn(accS[mt][nt][3]);
                g_H2[(size_t)d1 * DH + cA]     = __float2half_rn(accR[mt][nt][1]);
                g_H2[(size_t)d1 * DH + cA + 8] = __float2half_rn(accR[mt][nt][3]);
            }
        }
}

// ---------------- fused edge kernel (ldmatrix + fp16 mma) --------------------
__global__ void __launch_bounds__(EK_THREADS, 1)
edge_kernel(const float* __restrict__ h, const float* __restrict__ e,
            const int* __restrict__ senders, const int* __restrict__ receivers,
            const float* __restrict__ W1, const float* __restrict__ b1,
            const float* __restrict__ W2, const float* __restrict__ b2,
            const float* __restrict__ We, const float* __restrict__ be,
            float* __restrict__ out_e)
{
    extern __shared__ char smc[];
    uint32_t* W1w = (uint32_t*)(smc + OFF_W1E);
    uint32_t* W2w = (uint32_t*)(smc + OFF_W2);
    uint32_t* WEw = (uint32_t*)(smc + OFF_WE);
    uint32_t* b1h = (uint32_t*)(smc + OFF_BI1H);
    float* bi2 = (float*)(smc + OFF_BI2);
    float* bie = (float*)(smc + OFF_BIE);

    const int tid = threadIdx.x;

    // ---- stage weights (row-major in k, fp16x2 words) + biases --------------
    for (int i = tid; i < DH * 32; i += EK_THREADS) {         // W1e rows c, k 0..63
        int c = i >> 5, k2 = i & 31;
        W1w[c * 36 + k2] = packh2(W1[(2 * k2) * DH + c], W1[(2 * k2 + 1) * DH + c]);
    }
    for (int i = tid; i < D * (DH / 2); i += EK_THREADS) {
        int c = i >> 6, k2 = i & 63;
        W2w[c * 68 + k2] = packh2(W2[(2 * k2) * D + c], W2[(2 * k2 + 1) * D + c]);
        WEw[c * 68 + k2] = packh2(We[(2 * k2) * D + c], We[(2 * k2 + 1) * D + c]);
    }
    if (tid < D)  b1h[tid] = packh2(b1[2 * tid], b1[2 * tid + 1]);
    if (tid < D)  bi2[tid] = b2[tid];
    else if (tid < 2 * D) bie[tid - D] = be[tid - D];
    __syncthreads();

    // ---- group-local state ---------------------------------------------------
    const int gi   = tid >> 8;
    const int lt   = tid & 255;
    const int w    = lt >> 5;
    const int lane = lt & 31;
    const int g    = lane >> 2;
    const int tig  = lane & 3;

    char* gbase = smc + OFF_GRP + gi * GRP_BYTES;
    uint32_t* Xw   = (uint32_t*)gbase;
    __half*   Xh   = (__half*)gbase;
    uint32_t* HSRw = (uint32_t*)(gbase + GOFF_HSR);
    float*    mf   = (float*)(gbase + GOFF_MF);
    int*      ridx = (int*)(gbase + GOFF_RIDX);

    const uint32_t Xs  = (uint32_t)__cvta_generic_to_shared(Xw);
    const uint32_t W1s = (uint32_t)__cvta_generic_to_shared(W1w);
    const uint32_t W2s = (uint32_t)__cvta_generic_to_shared(W2w);
    const uint32_t WEs = (uint32_t)__cvta_generic_to_shared(WEw);

    const int c0w1 = (w & 3) * 32;
    const int e0w1 = (w >> 2) * 32;
    const int wl   = w & 3;
    const int c0w2 = (wl & 1) * 32;
    const int e0w2 = (wl >> 1) * 32;
    const int barid = gi + 1;

    // ldmatrix lane-address components
    const int rA  = (lane & 7) + ((lane >> 3) & 1) * 8;   // A: row within 16
    const int cA4 = (lane >> 4) << 2;                     // A: +4 words for k8..15
    const int rB  = (lane & 7) + ((lane >> 4) << 3);      // B: row within 16 (nt pair)
    const int cB4 = ((lane >> 3) & 1) << 2;               // B: +4 words for k8..15

    // per-warp ldmatrix base addresses (bytes)
    const uint32_t aW1b = W1s + ((c0w1 + rA) * 36 + cA4) * 4;   // +2304/mt, +32/kt
    const uint32_t aW2b = W2s + ((c0w2 + rA) * 68 + cA4) * 4;   // +4352/mt, +32/kt
    const uint32_t aWEb = WEs + ((c0w2 + rA) * 68 + cA4) * 4;
    const uint32_t bX1b = Xs + ((e0w1 + rB) * XSTRW + cB4) * 4; // +6400/ntp, +32/kt
    const uint32_t bX2b = Xs + ((e0w2 + rB) * XSTRW + cB4) * 4;

    #define BARG() asm volatile("bar.sync %0, 256;" :: "r"(barid) : "memory")

    for (int tile = blockIdx.x * 2 + gi; tile < N_TILES; tile += 2 * gridDim.x) {
        const int base = tile * TILE_E;
        BARG();   // S0

        // ====== gather: e -> X rows (fp16), H1[s]+H2[r]+b1 -> HSR pairs ======
        {
            const int el = lt & 63;
            const int p4 = lt >> 6;
            const int sI = senders[base + el];
            const int rI = receivers[base + el];
            if (p4 == 0) ridx[el] = rI;

            // e features: 16 floats -> 8 half2 words -> 2 STS.128
            const float4* ep = (const float4*)(e + (size_t)(base + el) * D) + p4 * 4;
            uint32_t ew[8];
            #pragma unroll
            for (int q = 0; q < 4; q++) {
                float4 v = ep[q];
                ew[2 * q]     = packh2(v.x, v.y);
                ew[2 * q + 1] = packh2(v.z, v.w);
            }
            uint4* xdst = (uint4*)(Xw + el * XSTRW + p4 * 8);
            xdst[0] = make_uint4(ew[0], ew[1], ew[2], ew[3]);
            xdst[1] = make_uint4(ew[4], ew[5], ew[6], ew[7]);

            // H-sum pairs: c in [p4*32, p4*32+32)
            const uint4* h1p = (const uint4*)(g_H1 + (size_t)sI * DH) + p4 * 4;
            const uint4* h2p = (const uint4*)(g_H2 + (size_t)rI * DH) + p4 * 4;
            uint32_t hw[16];
            #pragma unroll
            for (int q = 0; q < 4; q++) {
                uint4 a = h1p[q], b = h2p[q];
                const __half2* bb = (const __half2*)(b1h + (p4 * 4 + q) * 4);
                __half2 s0 = __hadd2(__hadd2(*(__half2*)&a.x, *(__half2*)&b.x), bb[0]);
                __half2 s1 = __hadd2(__hadd2(*(__half2*)&a.y, *(__half2*)&b.y), bb[1]);
                __half2 s2 = __hadd2(__hadd2(*(__half2*)&a.z, *(__half2*)&b.z), bb[2]);
                __half2 s3 = __hadd2(__hadd2(*(__half2*)&a.w, *(__half2*)&b.w), bb[3]);
                hw[q * 4 + 0] = *(uint32_t*)&s0;
                hw[q * 4 + 1] = *(uint32_t*)&s1;
                hw[q * 4 + 2] = *(uint32_t*)&s2;
                hw[q * 4 + 3] = *(uint32_t*)&s3;
            }
            // re-pair (c, c+8): blocks (0,1) and (2,3)
            uint32_t pw[16];
            #pragma unroll
            for (int bq = 0; bq < 2; bq++) {
                const __half2* s0 = (const __half2*)(hw + bq * 8);
                const __half2* s1 = (const __half2*)(hw + bq * 8 + 4);
                #pragma unroll
                for (int j = 0; j < 4; j++) {
                    __half2 lo = __lows2half2(s0[j], s1[j]);
                    __half2 hi = __highs2half2(s0[j], s1[j]);
                    pw[bq * 8 + 2 * j]     = *(uint32_t*)&lo;
                    pw[bq * 8 + 2 * j + 1] = *(uint32_t*)&hi;
                }
            }
            uint4* hdst = (uint4*)(HSRw + el * HSTRW + p4 * 16);
            hdst[0] = make_uint4(pw[0],  pw[1],  pw[2],  pw[3]);
            hdst[1] = make_uint4(pw[4],  pw[5],  pw[6],  pw[7]);
            hdst[2] = make_uint4(pw[8],  pw[9],  pw[10], pw[11]);
            hdst[3] = make_uint4(pw[12], pw[13], pw[14], pw[15]);
        }
        BARG();   // S1

        // ====== GEMM1': acc init = HSR(+b1); += e @ W1e (K=64) ===============
        float acc1[2][4][4];
        {
            const int cpb = 16 * (w & 3);   // pair-index base for c0w1
            #pragma unroll
            for (int mt = 0; mt < 2; mt++)
                #pragma unroll
                for (int nt = 0; nt < 4; nt++) {
                    int eA = e0w1 + 8 * nt + 2 * tig;
                    int cp = cpb + 8 * mt + g;
                    uint32_t v0 = HSRw[eA * HSTRW + cp];
                    uint32_t v1 = HSRw[(eA + 1) * HSTRW + cp];
                    float2 f0 = __half22float2(*(__half2*)&v0);
                    float2 f1 = __half22float2(*(__half2*)&v1);
                    acc1[mt][nt][0] = f0.x; acc1[mt][nt][2] = f0.y;
                    acc1[mt][nt][1] = f1.x; acc1[mt][nt][3] = f1.y;
                }
        }
        #pragma unroll
        for (int kt = 0; kt < 4; kt++) {
            uint32_t av[2][4], bv[2][4];
            ldsm4(av[0], aW1b + kt * 32);
            ldsm4(av[1], aW1b + 2304 + kt * 32);
            ldsm4(bv[0], bX1b + kt * 32);
            ldsm4(bv[1], bX1b + 6400 + kt * 32);
            #pragma unroll
            for (int mt = 0; mt < 2; mt++)
                #pragma unroll
                for (int np = 0; np < 2; np++) {
                    mma16(acc1[mt][2 * np],     av[mt], bv[np]);
                    mma16(acc1[mt][2 * np + 1], av[mt], bv[np] + 2);
                }
        }
        BARG();   // S2

        // ===== epilogue1: hid = relu(acc) -> X halves 64+c ===================
        #pragma unroll
        for (int mt = 0; mt < 2; mt++)
            #pragma unroll
            for (int nt = 0; nt < 4; nt++) {
                int cA = c0w1 + 16 * mt + g;
                int eA = e0w1 + 8 * nt + 2 * tig;
                Xh[eA * 200 + 64 + cA]           = __float2half_rn(fmaxf(acc1[mt][nt][0], 0.f));
                Xh[(eA + 1) * 200 + 64 + cA]     = __float2half_rn(fmaxf(acc1[mt][nt][1], 0.f));
                Xh[eA * 200 + 64 + cA + 8]       = __float2half_rn(fmaxf(acc1[mt][nt][2], 0.f));
                Xh[(eA + 1) * 200 + 64 + cA + 8] = __float2half_rn(fmaxf(acc1[mt][nt][3], 0.f));
            }
        BARG();   // S3

        // ===== warps0-3: GEMM2 (m = hid @ W2) | warps4-7: GEMM3a (e-part) ====
        float acc2[2][4][4];
        #pragma unroll
        for (int mt = 0; mt < 2; mt++)
            #pragma unroll
            for (int nt = 0; nt < 4; nt++)
                #pragma unroll
                for (int q = 0; q < 4; q++) acc2[mt][nt][q] = 0.f;

        if (w < 4) {
            #pragma unroll
            for (int kt = 0; kt < 8; kt++) {
                uint32_t av[2][4], bv[2][4];
                ldsm4(av[0], aW2b + kt * 32);
                ldsm4(av[1], aW2b + 4352 + kt * 32);
                ldsm4(bv[0], bX2b + 128 + kt * 32);          // hid at word 32
                ldsm4(bv[1], bX2b + 6400 + 128 + kt * 32);
                #pragma unroll
                for (int mt = 0; mt < 2; mt++)
                    #pragma unroll
                    for (int np = 0; np < 2; np++) {
                        mma16(acc2[mt][2 * np],     av[mt], bv[np]);
                        mma16(acc2[mt][2 * np + 1], av[mt], bv[np] + 2);
                    }
            }
        } else {
            #pragma unroll
            for (int kt = 0; kt < 4; kt++) {
                uint32_t av[2][4], bv[2][4];
                ldsm4(av[0], aWEb + kt * 32);
                ldsm4(av[1], aWEb + 4352 + kt * 32);
                ldsm4(bv[0], bX2b + kt * 32);                // e at word 0
                ldsm4(bv[1], bX2b + 6400 + kt * 32);
                #pragma unroll
                for (int mt = 0; mt < 2; mt++)
                    #pragma unroll
                    for (int np = 0; np < 2; np++) {
                        mma16(acc2[mt][2 * np],     av[mt], bv[np]);
                        mma16(acc2[mt][2 * np + 1], av[mt], bv[np] + 2);
                    }
            }
        }
        BARG();   // S4

        // ===== epilogue2 (w0-3): m -> X halves 64+c (fp16) + mf (fp32) =======
        if (w < 4) {
            #pragma unroll
            for (int mt = 0; mt < 2; mt++)
                #pragma unroll
                for (int nt = 0; nt < 4; nt++) {
                    int cA = c0w2 + 16 * mt + g;
                    int eA = e0w2 + 8 * nt + 2 * tig;
                    float v0 = acc2[mt][nt][0] + bi2[cA];
                    float v1 = acc2[mt][nt][1] + bi2[cA];
                    float v2 = acc2[mt][nt][2] + bi2[cA + 8];
                    float v3 = acc2[mt][nt][3] + bi2[cA + 8];
                    Xh[eA * 200 + 64 + cA]           = __float2half_rn(v0);
                    Xh[(eA + 1) * 200 + 64 + cA]     = __float2half_rn(v1);
                    Xh[eA * 200 + 64 + cA + 8]       = __float2half_rn(v2);
                    Xh[(eA + 1) * 200 + 64 + cA + 8] = __float2half_rn(v3);
                    mf[eA * HSTRW + cA]           = v0;
                    mf[(eA + 1) * HSTRW + cA]     = v1;
                    mf[eA * HSTRW + cA + 8]       = v2;
                    mf[(eA + 1) * HSTRW + cA + 8] = v3;
                }
        }
        BARG();   // S5

        if (w >= 4) {
            // ===== GEMM3b: += m @ We[64:128]  (m at X word 32..63) ===========
            #pragma unroll
            for (int kt = 4; kt < 8; kt++) {
                uint32_t av[2][4], bv[2][4];
                ldsm4(av[0], aWEb + kt * 32);
                ldsm4(av[1], aWEb + 4352 + kt * 32);
                ldsm4(bv[0], bX2b + 128 + (kt - 4) * 32);
                ldsm4(bv[1], bX2b + 6400 + 128 + (kt - 4) * 32);
                #pragma unroll
                for (int mt = 0; mt < 2; mt++)
                    #pragma unroll
                    for (int np = 0; np < 2; np++) {
                        mma16(acc2[mt][2 * np],     av[mt], bv[np]);
                        mma16(acc2[mt][2 * np + 1], av[mt], bv[np] + 2);
                    }
            }
            // ===== epilogue3: e_new = relu(acc+be) -> gmem ===================
            #pragma unroll
            for (int mt = 0; mt < 2; mt++)
                #pragma unroll
                for (int nt = 0; nt < 4; nt++) {
                    int cA = c0w2 + 16 * mt + g;
                    int eA = e0w2 + 8 * nt + 2 * tig;
                    float* d0 = out_e + (size_t)(base + eA) * D;
                    float* d1 = out_e + (size_t)(base + eA + 1) * D;
                    d0[cA]     = fmaxf(acc2[mt][nt][0] + bie[cA], 0.f);
                    d1[cA]     = fmaxf(acc2[mt][nt][1] + bie[cA], 0.f);
                    d0[cA + 8] = fmaxf(acc2[mt][nt][2] + bie[cA + 8], 0.f);
                    d1[cA + 8] = fmaxf(acc2[mt][nt][3] + bie[cA + 8], 0.f);
                }
        } else {
            // ===== scatter: atomicAdd m (fp32) into g_agg ====================
            const int el = lt & 63;
            const int hf = (lt >> 6) & 1;
            const int r  = ridx[el];
            const float* mrow = mf + el * HSTRW + hf * 32;
            float* dstp = g_agg + (size_t)r * D + hf * 32;
            #pragma unroll 8
            for (int c = 0; c < 32; c++) atomicAdd(dstp + c, mrow[c]);
        }
    }
    #undef BARG
}

// ---------------- node kernel: h_new = relu([h | agg] @ W_node + b) ----------
#define NT    32
#define NPAD  36
#define NOFF_W 0
#define NOFF_B (NOFF_W + DH * D)
#define NOFF_X (NOFF_B + D)
#define SMEM_NODE_FLOATS (NOFF_X + DH * NPAD)
#define SMEM_NODE_BYTES  (SMEM_NODE_FLOATS * 4)

__global__ void __launch_bounds__(128)
node_kernel(const float* __restrict__ h,
            const float* __restrict__ Wn, const float* __restrict__ bn,
            float* __restrict__ out_h)
{
    extern __shared__ float sm[];
    const int tid = threadIdx.x;

    for (int i = tid; i < DH * D / 4; i += 128)
        ((float4*)(sm + NOFF_W))[i] = ((const float4*)Wn)[i];
    if (tid < D) sm[NOFF_B + tid] = bn[tid];
    __syncthreads();

    const int nl   = tid >> 2;
    const int part = tid & 3;
    const int ng   = tid >> 4;
    const int cgc  = tid & 15;

    const int n_tiles = N_NODES / NT;
    for (int tile = blockIdx.x; tile < n_tiles; tile += gridDim.x) {
        const int base = tile * NT;
        {
            const float4* hp = (const float4*)(h + (size_t)(base + nl) * D) + part * 4;
            const float4* ap = (const float4*)(g_agg + (size_t)(base + nl) * D) + part * 4;
            #pragma unroll
            for (int q = 0; q < 4; q++) {
                float4 v = hp[q];
                int k0 = part * 16 + q * 4;
                sm[NOFF_X + (k0 + 0) * NPAD + nl] = v.x;
                sm[NOFF_X + (k0 + 1) * NPAD + nl] = v.y;
                sm[NOFF_X + (k0 + 2) * NPAD + nl] = v.z;
                sm[NOFF_X + (k0 + 3) * NPAD + nl] = v.w;
            }
            #pragma unroll
            for (int q = 0; q < 4; q++) {
                float4 v = ap[q];
                int k0 = 64 + part * 16 + q * 4;
                sm[NOFF_X + (k0 + 0) * NPAD + nl] = v.x;
                sm[NOFF_X + (k0 + 1) * NPAD + nl] = v.y;
                sm[NOFF_X + (k0 + 2) * NPAD + nl] = v.z;
                sm[NOFF_X + (k0 + 3) * NPAD + nl] = v.w;
            }
        }
        __syncthreads();

        float acc[4][4];
        #pragma unroll
        for (int i = 0; i < 4; i++)
            #pragma unroll
            for (int j = 0; j < 4; j++) acc[i][j] = 0.f;

        const float* Xb = sm + NOFF_X + ng * 4;
        const float* Wb = sm + NOFF_W + cgc * 4;
        #pragma unroll 4
        for (int k = 0; k < DH; k++) {
            float4 a = *(const float4*)(Xb + k * NPAD);
            float4 wv4 = *(const float4*)(Wb + k * D);
            float av[4] = {a.x, a.y, a.z, a.w};
            float wv[4] = {wv4.x, wv4.y, wv4.z, wv4.w};
            #pragma unroll
            for (int i = 0; i < 4; i++)
                #pragma unroll
                for (int j = 0; j < 4; j++)
                    acc[i][j] = fmaf(av[i], wv[j], acc[i][j]);
        }
        float bb[4];
        #pragma unroll
        for (int j = 0; j < 4; j++) bb[j] = sm[NOFF_B + cgc * 4 + j];
        #pragma unroll
        for (int i = 0; i < 4; i++) {
            float4 v;
            v.x = fmaxf(acc[i][0] + bb[0], 0.f);
            v.y = fmaxf(acc[i][1] + bb[1], 0.f);
            v.z = fmaxf(acc[i][2] + bb[2], 0.f);
            v.w = fmaxf(acc[i][3] + bb[3], 0.f);
            *(float4*)(out_h + (size_t)(base + ng * 4 + i) * D + cgc * 4) = v;
        }
        __syncthreads();
    }
}

// ---------------- launch -----------------------------------------------------
extern "C" void kernel_launch(void* const* d_in, const int* in_sizes, int n_in,
                              void* d_out, int out_size)
{
    const float* h        = (const float*)d_in[0];
    const float* e        = (const float*)d_in[1];
    const int*   senders  = (const int*)d_in[2];
    const int*   receivers= (const int*)d_in[3];
    const float* W1       = (const float*)d_in[4];
    const float* b1       = (const float*)d_in[5];
    const float* W2       = (const float*)d_in[6];
    const float* b2       = (const float*)d_in[7];
    const float* Wn       = (const float*)d_in[8];
    const float* bn       = (const float*)d_in[9];
    const float* We       = (const float*)d_in[10];
    const float* be       = (const float*)d_in[11];

    float* out_h = (float*)d_out;
    float* out_e = out_h + (size_t)N_NODES * D;

    cudaFuncSetAttribute(edge_kernel, cudaFuncAttributeMaxDynamicSharedMemorySize,
                         SMEM_EDGE_BYTES);
    cudaFuncSetAttribute(node_kernel, cudaFuncAttributeMaxDynamicSharedMemorySize,
                         SMEM_NODE_BYTES);

    zero_agg_kernel<<<(N_NODES * D / 4 + 255) / 256, 256>>>();
    pre_kernel<<<(N_NODES + 63) / 64, 256, SMEM_PRE_BYTES>>>(h, W1);
    edge_kernel<<<EK_GRID, EK_THREADS, SMEM_EDGE_BYTES>>>(
        h, e, senders, receivers, W1, b1, W2, b2, We, be, out_e);
    node_kernel<<<1480, 128, SMEM_NODE_BYTES>>>(h, Wn, bn, out_h);
}

// round 12
// speedup vs baseline: 1.3692x; 1.3290x over previous
#include <cuda_runtime.h>
#include <cuda_fp16.h>
#include <cstdint>

#define N_NODES 100000
#define N_EDGES 1600000
#define D       64
#define DH      128
#define KIN     192

#define TILE_E   64
#define N_TILES  (N_EDGES / TILE_E)   // 25000
#define EK_GRID  148
#define EK_THREADS 512                // 2 groups x 256

// ---------------- edge-kernel smem byte offsets ------------------------------
#define OFF_W1E   0          // W1e^T fp16 [128 rows][36 words] = 18432
#define OFF_W2    18432      // W2^T [64 rows][68 words] = 17408
#define OFF_WE    35840      // We^T [64 rows][68 words] = 17408
#define OFF_BI1H  53248      // b1 as half2 [64 words] = 256
#define OFF_BI2   53504      // 256
#define OFF_BIE   53760      // 256
#define OFF_GRP   54016
// group block: X 64x100 words 25600 | HSR 64x68 words 17408 | mf 17408 | ridx 256
#define GRP_BYTES 60672
#define GOFF_HSR  25600
#define GOFF_MF   43008
#define GOFF_RIDX 60416
#define SMEM_EDGE_BYTES (OFF_GRP + 2 * GRP_BYTES)   // 175360

#define XSTRW 100            // X row stride in words
#define HSTRW 68             // HSR/mf row stride in words

// ---------------- precompute-kernel smem -------------------------------------
#define POFF_WS   0
#define POFF_WR   18432
#define POFF_PL   36864
#define SMEM_PRE_BYTES 45056

// ---------------- helpers ----------------------------------------------------
__device__ __forceinline__ uint32_t packh2(float lo, float hi) {
    uint32_t d;
    asm("cvt.rn.f16x2.f32 %0, %1, %2;" : "=r"(d) : "f"(hi), "f"(lo));
    return d;
}
__device__ __forceinline__ void mma16(float* c, const uint32_t* a, const uint32_t* b) {
    asm volatile(
        "mma.sync.aligned.m16n8k16.row.col.f32.f16.f16.f32 "
        "{%0,%1,%2,%3}, {%4,%5,%6,%7}, {%8,%9}, {%0,%1,%2,%3};"
        : "+f"(c[0]), "+f"(c[1]), "+f"(c[2]), "+f"(c[3])
        : "r"(a[0]), "r"(a[1]), "r"(a[2]), "r"(a[3]), "r"(b[0]), "r"(b[1]));
}
__device__ __forceinline__ void ldsm4(uint32_t* r, uint32_t saddr) {
    asm volatile("ldmatrix.sync.aligned.m8n8.x4.shared.b16 {%0,%1,%2,%3}, [%4];"
        : "=r"(r[0]), "=r"(r[1]), "=r"(r[2]), "=r"(r[3]) : "r"(saddr));
}
__device__ __forceinline__ void red4(float* p, float4 v) {
    asm volatile("red.global.add.v4.f32 [%0], {%1,%2,%3,%4};"
        :: "l"(p), "f"(v.x), "f"(v.y), "f"(v.z), "f"(v.w) : "memory");
}

// ---------------- scratch ----------------------------------------------------
__device__ float  g_agg[(size_t)N_NODES * D];
__device__ __half g_H1[(size_t)N_NODES * DH];
__device__ __half g_H2[(size_t)N_NODES * DH];

__global__ void zero_agg_kernel() {
    size_t i = (size_t)blockIdx.x * blockDim.x + threadIdx.x;
    size_t n4 = (size_t)N_NODES * D / 4;
    if (i < n4) ((float4*)g_agg)[i] = make_float4(0.f, 0.f, 0.f, 0.f);
}

// ---------------- precompute: H1 = h@W1s, H2 = h@W1r -------------------------
__global__ void __launch_bounds__(256)
pre_kernel(const float* __restrict__ h, const float* __restrict__ W1)
{
    extern __shared__ char smc[];
    uint32_t* WSw = (uint32_t*)(smc + POFF_WS);
    uint32_t* WRw = (uint32_t*)(smc + POFF_WR);
    uint32_t* PW  = (uint32_t*)(smc + POFF_PL);

    const int tid  = threadIdx.x;
    const int w    = tid >> 5;
    const int lane = tid & 31;
    const int g    = lane >> 2;
    const int tig  = lane & 3;
    const int swz  = tig << 3;

    for (int i = tid; i < DH * 32; i += 256) {
        int c = i >> 5, k2 = i & 31;
        WSw[c * 36 + k2] = packh2(W1[(64 + 2 * k2) * DH + c],
                                  W1[(64 + 2 * k2 + 1) * DH + c]);
        WRw[c * 36 + k2] = packh2(W1[(128 + 2 * k2) * DH + c],
                                  W1[(128 + 2 * k2 + 1) * DH + c]);
    }
    __syncthreads();

    const int base = blockIdx.x * 64;
    {
        const int nl = tid & 63;
        const int p4 = tid >> 6;
        const int node = base + nl;
        #pragma unroll
        for (int q = 0; q < 4; q++) {
            float4 v = (node < N_NODES)
                ? ((const float4*)(h + (size_t)node * D))[p4 * 4 + q]
                : make_float4(0.f, 0.f, 0.f, 0.f);
            int p = p4 * 8 + q * 2;
            PW[p * 64 + (nl ^ ((p & 3) << 3))]             = packh2(v.x, v.y);
            PW[(p + 1) * 64 + (nl ^ (((p + 1) & 3) << 3))] = packh2(v.z, v.w);
        }
    }
    __syncthreads();

    const int c0 = (w & 3) * 32;
    const int n0 = (w >> 2) * 32;

    float accS[2][4][4], accR[2][4][4];
    #pragma unroll
    for (int mt = 0; mt < 2; mt++)
        #pragma unroll
        for (int nt = 0; nt < 4; nt++)
            #pragma unroll
            for (int q = 0; q < 4; q++) { accS[mt][nt][q] = 0.f; accR[mt][nt][q] = 0.f; }

    #pragma unroll
    for (int kt = 0; kt < 4; kt++) {
        const int k8 = kt * 8;
        uint32_t as[2][4], ar[2][4];
        #pragma unroll
        for (int mt = 0; mt < 2; mt++) {
            int r = c0 + 16 * mt + g;
            as[mt][0] = WSw[r * 36 + k8 + tig];
            as[mt][1] = WSw[(r + 8) * 36 + k8 + tig];
            as[mt][2] = WSw[r * 36 + k8 + tig + 4];
            as[mt][3] = WSw[(r + 8) * 36 + k8 + tig + 4];
            ar[mt][0] = WRw[r * 36 + k8 + tig];
            ar[mt][1] = WRw[(r + 8) * 36 + k8 + tig];
            ar[mt][2] = WRw[r * 36 + k8 + tig + 4];
            ar[mt][3] = WRw[(r + 8) * 36 + k8 + tig + 4];
        }
        uint32_t bv[4][2];
        const int p0 = k8 + tig;
        #pragma unroll
        for (int nt = 0; nt < 4; nt++) {
            int es = (n0 + nt * 8 + g) ^ swz;
            bv[nt][0] = PW[p0 * 64 + es];
            bv[nt][1] = PW[(p0 + 4) * 64 + es];
        }
        #pragma unroll
        for (int mt = 0; mt < 2; mt++)
            #pragma unroll
            for (int nt = 0; nt < 4; nt++) {
                mma16(accS[mt][nt], as[mt], bv[nt]);
                mma16(accR[mt][nt], ar[mt], bv[nt]);
            }
    }

    #pragma unroll
    for (int mt = 0; mt < 2; mt++)
        #pragma unroll
        for (int nt = 0; nt < 4; nt++) {
            int cA = c0 + 16 * mt + g;
            int nA = n0 + 8 * nt + 2 * tig;
            int d0 = base + nA, d1 = base + nA + 1;
            if (d0 < N_NODES) {
                g_H1[(size_t)d0 * DH + cA]     = __float2half_rn(accS[mt][nt][0]);
                g_H1[(size_t)d0 * DH + cA + 8] = __float2half_rn(accS[mt][nt][2]);
                g_H2[(size_t)d0 * DH + cA]     = __float2half_rn(accR[mt][nt][0]);
                g_H2[(size_t)d0 * DH + cA + 8] = __float2half_rn(accR[mt][nt][2]);
            }
            if (d1 < N_NODES) {
                g_H1[(size_t)d1 * DH + cA]     = __float2half_rn(accS[mt][nt][1]);
                g_H1[(size_t)d1 * DH + cA + 8] = __float2half_rn(accS[mt][nt][3]);
                g_H2[(size_t)d1 * DH + cA]     = __float2half_rn(accR[mt][nt][1]);
                g_H2[(size_t)d1 * DH + cA + 8] = __float2half_rn(accR[mt][nt][3]);
            }
        }
}

// ---------------- fused edge kernel (ldmatrix + fp16 mma) --------------------
__global__ void __launch_bounds__(EK_THREADS, 1)
edge_kernel(const float* __restrict__ h, const float* __restrict__ e,
            const int* __restrict__ senders, const int* __restrict__ receivers,
            const float* __restrict__ W1, const float* __restrict__ b1,
            const float* __restrict__ W2, const float* __restrict__ b2,
            const float* __restrict__ We, const float* __restrict__ be,
            float* __restrict__ out_e)
{
    extern __shared__ char smc[];
    uint32_t* W1w = (uint32_t*)(smc + OFF_W1E);
    uint32_t* W2w = (uint32_t*)(smc + OFF_W2);
    uint32_t* WEw = (uint32_t*)(smc + OFF_WE);
    uint32_t* b1h = (uint32_t*)(smc + OFF_BI1H);
    float* bi2 = (float*)(smc + OFF_BI2);
    float* bie = (float*)(smc + OFF_BIE);

    const int tid = threadIdx.x;

    // ---- stage weights (row-major in k, fp16x2 words) + biases --------------
    for (int i = tid; i < DH * 32; i += EK_THREADS) {
        int c = i >> 5, k2 = i & 31;
        W1w[c * 36 + k2] = packh2(W1[(2 * k2) * DH + c], W1[(2 * k2 + 1) * DH + c]);
    }
    for (int i = tid; i < D * (DH / 2); i += EK_THREADS) {
        int c = i >> 6, k2 = i & 63;
        W2w[c * 68 + k2] = packh2(W2[(2 * k2) * D + c], W2[(2 * k2 + 1) * D + c]);
        WEw[c * 68 + k2] = packh2(We[(2 * k2) * D + c], We[(2 * k2 + 1) * D + c]);
    }
    if (tid < D)  b1h[tid] = packh2(b1[2 * tid], b1[2 * tid + 1]);
    if (tid < D)  bi2[tid] = b2[tid];
    else if (tid < 2 * D) bie[tid - D] = be[tid - D];
    __syncthreads();

    // ---- group-local state ---------------------------------------------------
    const int gi   = tid >> 8;
    const int lt   = tid & 255;
    const int w    = lt >> 5;
    const int lane = lt & 31;
    const int g    = lane >> 2;
    const int tig  = lane & 3;

    char* gbase = smc + OFF_GRP + gi * GRP_BYTES;
    uint32_t* Xw   = (uint32_t*)gbase;
    __half*   Xh   = (__half*)gbase;
    uint32_t* HSRw = (uint32_t*)(gbase + GOFF_HSR);
    float*    mf   = (float*)(gbase + GOFF_MF);
    int*      ridx = (int*)(gbase + GOFF_RIDX);

    const uint32_t Xs  = (uint32_t)__cvta_generic_to_shared(Xw);
    const uint32_t W1s = (uint32_t)__cvta_generic_to_shared(W1w);
    const uint32_t W2s = (uint32_t)__cvta_generic_to_shared(W2w);
    const uint32_t WEs = (uint32_t)__cvta_generic_to_shared(WEw);

    const int c0w1 = (w & 3) * 32;
    const int e0w1 = (w >> 2) * 32;
    const int wl   = w & 3;
    const int c0w2 = (wl & 1) * 32;
    const int e0w2 = (wl >> 1) * 32;
    const int barid = gi + 1;

    // ldmatrix lane-address components
    const int rA  = (lane & 7) + ((lane >> 3) & 1) * 8;
    const int cA4 = (lane >> 4) << 2;
    const int rB  = (lane & 7) + ((lane >> 4) << 3);
    const int cB4 = ((lane >> 3) & 1) << 2;

    const uint32_t aW1b = W1s + ((c0w1 + rA) * 36 + cA4) * 4;
    const uint32_t aW2b = W2s + ((c0w2 + rA) * 68 + cA4) * 4;
    const uint32_t aWEb = WEs + ((c0w2 + rA) * 68 + cA4) * 4;
    const uint32_t bX1b = Xs + ((e0w1 + rB) * XSTRW + cB4) * 4;
    const uint32_t bX2b = Xs + ((e0w2 + rB) * XSTRW + cB4) * 4;

    #define BARG() asm volatile("bar.sync %0, 256;" :: "r"(barid) : "memory")

    for (int tile = blockIdx.x * 2 + gi; tile < N_TILES; tile += 2 * gridDim.x) {
        const int base = tile * TILE_E;
        BARG();   // S0

        // ====== gather: e -> X rows (fp16), H1[s]+H2[r]+b1 -> HSR pairs ======
        {
            const int el = lt & 63;
            const int p4 = lt >> 6;
            const int sI = senders[base + el];
            const int rI = receivers[base + el];
            if (p4 == 0) ridx[el] = rI;

            const float4* ep = (const float4*)(e + (size_t)(base + el) * D) + p4 * 4;
            uint32_t ew[8];
            #pragma unroll
            for (int q = 0; q < 4; q++) {
                float4 v = ep[q];
                ew[2 * q]     = packh2(v.x, v.y);
                ew[2 * q + 1] = packh2(v.z, v.w);
            }
            uint4* xdst = (uint4*)(Xw + el * XSTRW + p4 * 8);
            xdst[0] = make_uint4(ew[0], ew[1], ew[2], ew[3]);
            xdst[1] = make_uint4(ew[4], ew[5], ew[6], ew[7]);

            const uint4* h1p = (const uint4*)(g_H1 + (size_t)sI * DH) + p4 * 4;
            const uint4* h2p = (const uint4*)(g_H2 + (size_t)rI * DH) + p4 * 4;
            uint32_t hw[16];
            #pragma unroll
            for (int q = 0; q < 4; q++) {
                uint4 a = h1p[q], b = h2p[q];
                const __half2* bb = (const __half2*)(b1h + (p4 * 4 + q) * 4);
                __half2 s0 = __hadd2(__hadd2(*(__half2*)&a.x, *(__half2*)&b.x), bb[0]);
                __half2 s1 = __hadd2(__hadd2(*(__half2*)&a.y, *(__half2*)&b.y), bb[1]);
                __half2 s2 = __hadd2(__hadd2(*(__half2*)&a.z, *(__half2*)&b.z), bb[2]);
                __half2 s3 = __hadd2(__hadd2(*(__half2*)&a.w, *(__half2*)&b.w), bb[3]);
                hw[q * 4 + 0] = *(uint32_t*)&s0;
                hw[q * 4 + 1] = *(uint32_t*)&s1;
                hw[q * 4 + 2] = *(uint32_t*)&s2;
                hw[q * 4 + 3] = *(uint32_t*)&s3;
            }
            uint32_t pw[16];
            #pragma unroll
            for (int bq = 0; bq < 2; bq++) {
                const __half2* s0 = (const __half2*)(hw + bq * 8);
                const __half2* s1 = (const __half2*)(hw + bq * 8 + 4);
                #pragma unroll
                for (int j = 0; j < 4; j++) {
                    __half2 lo = __lows2half2(s0[j], s1[j]);
                    __half2 hi = __highs2half2(s0[j], s1[j]);
                    pw[bq * 8 + 2 * j]     = *(uint32_t*)&lo;
                    pw[bq * 8 + 2 * j + 1] = *(uint32_t*)&hi;
                }
            }
            uint4* hdst = (uint4*)(HSRw + el * HSTRW + p4 * 16);
            hdst[0] = make_uint4(pw[0],  pw[1],  pw[2],  pw[3]);
            hdst[1] = make_uint4(pw[4],  pw[5],  pw[6],  pw[7]);
            hdst[2] = make_uint4(pw[8],  pw[9],  pw[10], pw[11]);
            hdst[3] = make_uint4(pw[12], pw[13], pw[14], pw[15]);
        }
        BARG();   // S1

        // ====== GEMM1': acc init = HSR(+b1); += e @ W1e (K=64) ===============
        float acc1[2][4][4];
        {
            const int cpb = 16 * (w & 3);
            #pragma unroll
            for (int mt = 0; mt < 2; mt++)
                #pragma unroll
                for (int nt = 0; nt < 4; nt++) {
                    int eA = e0w1 + 8 * nt + 2 * tig;
                    int cp = cpb + 8 * mt + g;
                    uint32_t v0 = HSRw[eA * HSTRW + cp];
                    uint32_t v1 = HSRw[(eA + 1) * HSTRW + cp];
                    float2 f0 = __half22float2(*(__half2*)&v0);
                    float2 f1 = __half22float2(*(__half2*)&v1);
                    acc1[mt][nt][0] = f0.x; acc1[mt][nt][2] = f0.y;
                    acc1[mt][nt][1] = f1.x; acc1[mt][nt][3] = f1.y;
                }
        }
        #pragma unroll
        for (int kt = 0; kt < 4; kt++) {
            uint32_t av[2][4], bv[2][4];
            ldsm4(av[0], aW1b + kt * 32);
            ldsm4(av[1], aW1b + 2304 + kt * 32);
            ldsm4(bv[0], bX1b + kt * 32);
            ldsm4(bv[1], bX1b + 6400 + kt * 32);
            #pragma unroll
            for (int mt = 0; mt < 2; mt++)
                #pragma unroll
                for (int np = 0; np < 2; np++) {
                    mma16(acc1[mt][2 * np],     av[mt], bv[np]);
                    mma16(acc1[mt][2 * np + 1], av[mt], bv[np] + 2);
                }
        }
        BARG();   // S2

        // ===== epilogue1: hid = relu(acc) -> X halves 64+c ===================
        #pragma unroll
        for (int mt = 0; mt < 2; mt++)
            #pragma unroll
            for (int nt = 0; nt < 4; nt++) {
                int cA = c0w1 + 16 * mt + g;
                int eA = e0w1 + 8 * nt + 2 * tig;
                Xh[eA * 200 + 64 + cA]           = __float2half_rn(fmaxf(acc1[mt][nt][0], 0.f));
                Xh[(eA + 1) * 200 + 64 + cA]     = __float2half_rn(fmaxf(acc1[mt][nt][1], 0.f));
                Xh[eA * 200 + 64 + cA + 8]       = __float2half_rn(fmaxf(acc1[mt][nt][2], 0.f));
                Xh[(eA + 1) * 200 + 64 + cA + 8] = __float2half_rn(fmaxf(acc1[mt][nt][3], 0.f));
            }
        BARG();   // S3

        // ===== warps0-3: GEMM2 (m = hid @ W2) | warps4-7: GEMM3a (e-part) ====
        float acc2[2][4][4];
        #pragma unroll
        for (int mt = 0; mt < 2; mt++)
            #pragma unroll
            for (int nt = 0; nt < 4; nt++)
                #pragma unroll
                for (int q = 0; q < 4; q++) acc2[mt][nt][q] = 0.f;

        if (w < 4) {
            #pragma unroll
            for (int kt = 0; kt < 8; kt++) {
                uint32_t av[2][4], bv[2][4];
                ldsm4(av[0], aW2b + kt * 32);
                ldsm4(av[1], aW2b + 4352 + kt * 32);
                ldsm4(bv[0], bX2b + 128 + kt * 32);
                ldsm4(bv[1], bX2b + 6400 + 128 + kt * 32);
                #pragma unroll
                for (int mt = 0; mt < 2; mt++)
                    #pragma unroll
                    for (int np = 0; np < 2; np++) {
                        mma16(acc2[mt][2 * np],     av[mt], bv[np]);
                        mma16(acc2[mt][2 * np + 1], av[mt], bv[np] + 2);
                    }
            }
        } else {
            #pragma unroll
            for (int kt = 0; kt < 4; kt++) {
                uint32_t av[2][4], bv[2][4];
                ldsm4(av[0], aWEb + kt * 32);
                ldsm4(av[1], aWEb + 4352 + kt * 32);
                ldsm4(bv[0], bX2b + kt * 32);
                ldsm4(bv[1], bX2b + 6400 + kt * 32);
                #pragma unroll
                for (int mt = 0; mt < 2; mt++)
                    #pragma unroll
                    for (int np = 0; np < 2; np++) {
                        mma16(acc2[mt][2 * np],     av[mt], bv[np]);
                        mma16(acc2[mt][2 * np + 1], av[mt], bv[np] + 2);
                    }
            }
        }
        BARG();   // S4

        // ===== epilogue2 (w0-3): m -> X halves 64+c (fp16) + mf (fp32) =======
        if (w < 4) {
            #pragma unroll
            for (int mt = 0; mt < 2; mt++)
                #pragma unroll
                for (int nt = 0; nt < 4; nt++) {
                    int cA = c0w2 + 16 * mt + g;
                    int eA = e0w2 + 8 * nt + 2 * tig;
                    float v0 = acc2[mt][nt][0] + bi2[cA];
                    float v1 = acc2[mt][nt][1] + bi2[cA];
                    float v2 = acc2[mt][nt][2] + bi2[cA + 8];
                    float v3 = acc2[mt][nt][3] + bi2[cA + 8];
                    Xh[eA * 200 + 64 + cA]           = __float2half_rn(v0);
                    Xh[(eA + 1) * 200 + 64 + cA]     = __float2half_rn(v1);
                    Xh[eA * 200 + 64 + cA + 8]       = __float2half_rn(v2);
                    Xh[(eA + 1) * 200 + 64 + cA + 8] = __float2half_rn(v3);
                    mf[eA * HSTRW + cA]           = v0;
                    mf[(eA + 1) * HSTRW + cA]     = v1;
                    mf[eA * HSTRW + cA + 8]       = v2;
                    mf[(eA + 1) * HSTRW + cA + 8] = v3;
                }
        }
        BARG();   // S5

        if (w >= 4) {
            // ===== GEMM3b: += m @ We[64:128]  (m at X word 32..63) ===========
            #pragma unroll
            for (int kt = 4; kt < 8; kt++) {
                uint32_t av[2][4], bv[2][4];
                ldsm4(av[0], aWEb + kt * 32);
                ldsm4(av[1], aWEb + 4352 + kt * 32);
                ldsm4(bv[0], bX2b + 128 + (kt - 4) * 32);
                ldsm4(bv[1], bX2b + 6400 + 128 + (kt - 4) * 32);
                #pragma unroll
                for (int mt = 0; mt < 2; mt++)
                    #pragma unroll
                    for (int np = 0; np < 2; np++) {
                        mma16(acc2[mt][2 * np],     av[mt], bv[np]);
                        mma16(acc2[mt][2 * np + 1], av[mt], bv[np] + 2);
                    }
            }
            // ===== epilogue3: e_new = relu(acc+be) -> gmem ===================
            #pragma unroll
            for (int mt = 0; mt < 2; mt++)
                #pragma unroll
                for (int nt = 0; nt < 4; nt++) {
                    int cA = c0w2 + 16 * mt + g;
                    int eA = e0w2 + 8 * nt + 2 * tig;
                    float* d0 = out_e + (size_t)(base + eA) * D;
                    float* d1 = out_e + (size_t)(base + eA + 1) * D;
                    d0[cA]     = fmaxf(acc2[mt][nt][0] + bie[cA], 0.f);
                    d1[cA]     = fmaxf(acc2[mt][nt][1] + bie[cA], 0.f);
                    d0[cA + 8] = fmaxf(acc2[mt][nt][2] + bie[cA + 8], 0.f);
                    d1[cA + 8] = fmaxf(acc2[mt][nt][3] + bie[cA + 8], 0.f);
                }
        } else {
            // ===== scatter: red.global.add.v4.f32 m into g_agg ===============
            const int el = lt & 63;
            const int hf = (lt >> 6) & 1;
            const int r  = ridx[el];
            const float4* mrow4 = (const float4*)(mf + el * HSTRW + hf * 32);
            float* dstp = g_agg + (size_t)r * D + hf * 32;
            #pragma unroll
            for (int c4 = 0; c4 < 8; c4++)
                red4(dstp + c4 * 4, mrow4[c4]);
        }
    }
    #undef BARG
}

// ---------------- node kernel: h_new = relu([h | agg] @ W_node + b) ----------
#define NT    32
#define NPAD  36
#define NOFF_W 0
#define NOFF_B (NOFF_W + DH * D)
#define NOFF_X (NOFF_B + D)
#define SMEM_NODE_FLOATS (NOFF_X + DH * NPAD)
#define SMEM_NODE_BYTES  (SMEM_NODE_FLOATS * 4)

__global__ void __launch_bounds__(128)
node_kernel(const float* __restrict__ h,
            const float* __restrict__ Wn, const float* __restrict__ bn,
            float* __restrict__ out_h)
{
    extern __shared__ float sm[];
    const int tid = threadIdx.x;

    for (int i = tid; i < DH * D / 4; i += 128)
        ((float4*)(sm + NOFF_W))[i] = ((const float4*)Wn)[i];
    if (tid < D) sm[NOFF_B + tid] = bn[tid];
    __syncthreads();

    const int nl   = tid >> 2;
    const int part = tid & 3;
    const int ng   = tid >> 4;
    const int cgc  = tid & 15;

    const int n_tiles = N_NODES / NT;
    for (int tile = blockIdx.x; tile < n_tiles; tile += gridDim.x) {
        const int base = tile * NT;
        {
            const float4* hp = (const float4*)(h + (size_t)(base + nl) * D) + part * 4;
            const float4* ap = (const float4*)(g_agg + (size_t)(base + nl) * D) + part * 4;
            #pragma unroll
            for (int q = 0; q < 4; q++) {
                float4 v = hp[q];
                int k0 = part * 16 + q * 4;
                sm[NOFF_X + (k0 + 0) * NPAD + nl] = v.x;
                sm[NOFF_X + (k0 + 1) * NPAD + nl] = v.y;
                sm[NOFF_X + (k0 + 2) * NPAD + nl] = v.z;
                sm[NOFF_X + (k0 + 3) * NPAD + nl] = v.w;
            }
            #pragma unroll
            for (int q = 0; q < 4; q++) {
                float4 v = ap[q];
                int k0 = 64 + part * 16 + q * 4;
                sm[NOFF_X + (k0 + 0) * NPAD + nl] = v.x;
                sm[NOFF_X + (k0 + 1) * NPAD + nl] = v.y;
                sm[NOFF_X + (k0 + 2) * NPAD + nl] = v.z;
                sm[NOFF_X + (k0 + 3) * NPAD + nl] = v.w;
            }
        }
        __syncthreads();

        float acc[4][4];
        #pragma unroll
        for (int i = 0; i < 4; i++)
            #pragma unroll
            for (int j = 0; j < 4; j++) acc[i][j] = 0.f;

        const float* Xb = sm + NOFF_X + ng * 4;
        const float* Wb = sm + NOFF_W + cgc * 4;
        #pragma unroll 4
        for (int k = 0; k < DH; k++) {
            float4 a = *(const float4*)(Xb + k * NPAD);
            float4 wv4 = *(const float4*)(Wb + k * D);
            float av[4] = {a.x, a.y, a.z, a.w};
            float wv[4] = {wv4.x, wv4.y, wv4.z, wv4.w};
            #pragma unroll
            for (int i = 0; i < 4; i++)
                #pragma unroll
                for (int j = 0; j < 4; j++)
                    acc[i][j] = fmaf(av[i], wv[j], acc[i][j]);
        }
        float bb[4];
        #pragma unroll
        for (int j = 0; j < 4; j++) bb[j] = sm[NOFF_B + cgc * 4 + j];
        #pragma unroll
        for (int i = 0; i < 4; i++) {
            float4 v;
            v.x = fmaxf(acc[i][0] + bb[0], 0.f);
            v.y = fmaxf(acc[i][1] + bb[1], 0.f);
            v.z = fmaxf(acc[i][2] + bb[2], 0.f);
            v.w = fmaxf(acc[i][3] + bb[3], 0.f);
            *(float4*)(out_h + (size_t)(base + ng * 4 + i) * D + cgc * 4) = v;
        }
        __syncthreads();
    }
}

// ---------------- launch -----------------------------------------------------
extern "C" void kernel_launch(void* const* d_in, const int* in_sizes, int n_in,
                              void* d_out, int out_size)
{
    const float* h        = (const float*)d_in[0];
    const float* e        = (const float*)d_in[1];
    const int*   senders  = (const int*)d_in[2];
    const int*   receivers= (const int*)d_in[3];
    const float* W1       = (const float*)d_in[4];
    const float* b1       = (const float*)d_in[5];
    const float* W2       = (const float*)d_in[6];
    const float* b2       = (const float*)d_in[7];
    const float* Wn       = (const float*)d_in[8];
    const float* bn       = (const float*)d_in[9];
    const float* We       = (const float*)d_in[10];
    const float* be       = (const float*)d_in[11];

    float* out_h = (float*)d_out;
    float* out_e = out_h + (size_t)N_NODES * D;

    cudaFuncSetAttribute(edge_kernel, cudaFuncAttributeMaxDynamicSharedMemorySize,
                         SMEM_EDGE_BYTES);
    cudaFuncSetAttribute(node_kernel, cudaFuncAttributeMaxDynamicSharedMemorySize,
                         SMEM_NODE_BYTES);

    zero_agg_kernel<<<(N_NODES * D / 4 + 255) / 256, 256>>>();
    pre_kernel<<<(N_NODES + 63) / 64, 256, SMEM_PRE_BYTES>>>(h, W1);
    edge_kernel<<<EK_GRID, EK_THREADS, SMEM_EDGE_BYTES>>>(
        h, e, senders, receivers, W1, b1, W2, b2, We, be, out_e);
    node_kernel<<<1480, 128, SMEM_NODE_BYTES>>>(h, Wn, bn, out_h);
}

// round 13
// speedup vs baseline: 1.3772x; 1.0058x over previous
#include <cuda_runtime.h>
#include <cuda_fp16.h>
#include <cstdint>

#define N_NODES 100000
#define N_EDGES 1600000
#define D       64
#define DH      128
#define KIN     192

#define TILE_E   64
#define N_TILES  (N_EDGES / TILE_E)   // 25000
#define EK_GRID  148
#define EK_THREADS 512                // 2 groups x 256

// ---------------- edge-kernel smem byte offsets ------------------------------
#define OFF_W1E   0          // W1e^T fp16 [128 rows][36 w] = 18432
#define OFF_W2    18432      // W2^T [64 rows][68 w] = 17408
#define OFF_WEE   35840      // We_e^T (K=64) [64 rows][36 w] = 9216
#define OFF_P     45056      // P^T = (W2@We_m)^T [64 rows][68 w] = 17408
#define OFF_BI1H  62464      // b1 half2 = 256
#define OFF_BI2   62720      // b2 fp32 = 256
#define OFF_BIE2  62976      // be' fp32 = 256
#define OFF_GRP   63232
// group block: X 64x100 words 25600 | HSR/mf (overlaid) 64x68 words 17408 | ridx 256
#define GRP_BYTES 43264
#define GOFF_HSR  25600
#define GOFF_RIDX 43008
#define SMEM_EDGE_BYTES (OFF_GRP + 2 * GRP_BYTES)   // 149760

#define XSTRW 100            // X row stride in words
#define HSTRW 68             // HSR/mf row stride in words

// ---------------- precompute-kernel smem -------------------------------------
#define POFF_WS   0
#define POFF_WR   18432
#define POFF_PL   36864
#define SMEM_PRE_BYTES 45056

// ---------------- helpers ----------------------------------------------------
__device__ __forceinline__ uint32_t packh2(float lo, float hi) {
    uint32_t d;
    asm("cvt.rn.f16x2.f32 %0, %1, %2;" : "=r"(d) : "f"(hi), "f"(lo));
    return d;
}
__device__ __forceinline__ void mma16(float* c, const uint32_t* a, const uint32_t* b) {
    asm volatile(
        "mma.sync.aligned.m16n8k16.row.col.f32.f16.f16.f32 "
        "{%0,%1,%2,%3}, {%4,%5,%6,%7}, {%8,%9}, {%0,%1,%2,%3};"
        : "+f"(c[0]), "+f"(c[1]), "+f"(c[2]), "+f"(c[3])
        : "r"(a[0]), "r"(a[1]), "r"(a[2]), "r"(a[3]), "r"(b[0]), "r"(b[1]));
}
__device__ __forceinline__ void ldsm4(uint32_t* r, uint32_t saddr) {
    asm volatile("ldmatrix.sync.aligned.m8n8.x4.shared.b16 {%0,%1,%2,%3}, [%4];"
        : "=r"(r[0]), "=r"(r[1]), "=r"(r[2]), "=r"(r[3]) : "r"(saddr));
}
__device__ __forceinline__ void red4(float* p, float4 v) {
    asm volatile("red.global.add.v4.f32 [%0], {%1,%2,%3,%4};"
        :: "l"(p), "f"(v.x), "f"(v.y), "f"(v.z), "f"(v.w) : "memory");
}

// ---------------- scratch ----------------------------------------------------
__device__ float  g_agg[(size_t)N_NODES * D];
__device__ __half g_H1[(size_t)N_NODES * DH];
__device__ __half g_H2[(size_t)N_NODES * DH];
__device__ __half g_P[DH * D];      // W2 @ We_m  (fp16)
__device__ float  g_be2[D];         // b2 @ We_m + be

__global__ void zero_agg_kernel() {
    size_t i = (size_t)blockIdx.x * blockDim.x + threadIdx.x;
    size_t n4 = (size_t)N_NODES * D / 4;
    if (i < n4) ((float4*)g_agg)[i] = make_float4(0.f, 0.f, 0.f, 0.f);
}

// ---------------- tiny: P = W2 @ We_m,  be' = b2 @ We_m + be -----------------
__global__ void __launch_bounds__(256)
pw_kernel(const float* __restrict__ W2, const float* __restrict__ We,
          const float* __restrict__ b2, const float* __restrict__ be)
{
    int i = blockIdx.x * 256 + threadIdx.x;
    if (i < DH * D) {
        int k = i / D, c = i % D;
        float s = 0.f;
        #pragma unroll 8
        for (int l = 0; l < D; l++)
            s += W2[k * D + l] * We[(D + l) * D + c];
        g_P[k * D + c] = __float2half_rn(s);
    }
    if (i < D) {
        float s = be[i];
        #pragma unroll 8
        for (int l = 0; l < D; l++)
            s += b2[l] * We[(D + l) * D + i];
        g_be2[i] = s;
    }
}

// ---------------- precompute: H1 = h@W1s, H2 = h@W1r -------------------------
__global__ void __launch_bounds__(256)
pre_kernel(const float* __restrict__ h, const float* __restrict__ W1)
{
    extern __shared__ char smc[];
    uint32_t* WSw = (uint32_t*)(smc + POFF_WS);
    uint32_t* WRw = (uint32_t*)(smc + POFF_WR);
    uint32_t* PW  = (uint32_t*)(smc + POFF_PL);

    const int tid  = threadIdx.x;
    const int w    = tid >> 5;
    const int lane = tid & 31;
    const int g    = lane >> 2;
    const int tig  = lane & 3;
    const int swz  = tig << 3;

    for (int i = tid; i < DH * 32; i += 256) {
        int c = i >> 5, k2 = i & 31;
        WSw[c * 36 + k2] = packh2(W1[(64 + 2 * k2) * DH + c],
                                  W1[(64 + 2 * k2 + 1) * DH + c]);
        WRw[c * 36 + k2] = packh2(W1[(128 + 2 * k2) * DH + c],
                                  W1[(128 + 2 * k2 + 1) * DH + c]);
    }
    __syncthreads();

    const int base = blockIdx.x * 64;
    {
        const int nl = tid & 63;
        const int p4 = tid >> 6;
        const int node = base + nl;
        #pragma unroll
        for (int q = 0; q < 4; q++) {
            float4 v = (node < N_NODES)
                ? ((const float4*)(h + (size_t)node * D))[p4 * 4 + q]
                : make_float4(0.f, 0.f, 0.f, 0.f);
            int p = p4 * 8 + q * 2;
            PW[p * 64 + (nl ^ ((p & 3) << 3))]             = packh2(v.x, v.y);
            PW[(p + 1) * 64 + (nl ^ (((p + 1) & 3) << 3))] = packh2(v.z, v.w);
        }
    }
    __syncthreads();

    const int c0 = (w & 3) * 32;
    const int n0 = (w >> 2) * 32;

    float accS[2][4][4], accR[2][4][4];
    #pragma unroll
    for (int mt = 0; mt < 2; mt++)
        #pragma unroll
        for (int nt = 0; nt < 4; nt++)
            #pragma unroll
            for (int q = 0; q < 4; q++) { accS[mt][nt][q] = 0.f; accR[mt][nt][q] = 0.f; }

    #pragma unroll
    for (int kt = 0; kt < 4; kt++) {
        const int k8 = kt * 8;
        uint32_t as[2][4], ar[2][4];
        #pragma unroll
        for (int mt = 0; mt < 2; mt++) {
            int r = c0 + 16 * mt + g;
            as[mt][0] = WSw[r * 36 + k8 + tig];
            as[mt][1] = WSw[(r + 8) * 36 + k8 + tig];
            as[mt][2] = WSw[r * 36 + k8 + tig + 4];
            as[mt][3] = WSw[(r + 8) * 36 + k8 + tig + 4];
            ar[mt][0] = WRw[r * 36 + k8 + tig];
            ar[mt][1] = WRw[(r + 8) * 36 + k8 + tig];
            ar[mt][2] = WRw[r * 36 + k8 + tig + 4];
            ar[mt][3] = WRw[(r + 8) * 36 + k8 + tig + 4];
        }
        uint32_t bv[4][2];
        const int p0 = k8 + tig;
        #pragma unroll
        for (int nt = 0; nt < 4; nt++) {
            int es = (n0 + nt * 8 + g) ^ swz;
            bv[nt][0] = PW[p0 * 64 + es];
            bv[nt][1] = PW[(p0 + 4) * 64 + es];
        }
        #pragma unroll
        for (int mt = 0; mt < 2; mt++)
            #pragma unroll
            for (int nt = 0; nt < 4; nt++) {
                mma16(accS[mt][nt], as[mt], bv[nt]);
                mma16(accR[mt][nt], ar[mt], bv[nt]);
            }
    }

    #pragma unroll
    for (int mt = 0; mt < 2; mt++)
        #pragma unroll
        for (int nt = 0; nt < 4; nt++) {
            int cA = c0 + 16 * mt + g;
            int nA = n0 + 8 * nt + 2 * tig;
            int d0 = base + nA, d1 = base + nA + 1;
            if (d0 < N_NODES) {
                g_H1[(size_t)d0 * DH + cA]     = __float2half_rn(accS[mt][nt][0]);
                g_H1[(size_t)d0 * DH + cA + 8] = __float2half_rn(accS[mt][nt][2]);
                g_H2[(size_t)d0 * DH + cA]     = __float2half_rn(accR[mt][nt][0]);
                g_H2[(size_t)d0 * DH + cA + 8] = __float2half_rn(accR[mt][nt][2]);
            }
            if (d1 < N_NODES) {
                g_H1[(size_t)d1 * DH + cA]     = __float2half_rn(accS[mt][nt][1]);
                g_H1[(size_t)d1 * DH + cA + 8] = __float2half_rn(accS[mt][nt][3]);
                g_H2[(size_t)d1 * DH + cA]     = __float2half_rn(accR[mt][nt][1]);
                g_H2[(size_t)d1 * DH + cA + 8] = __float2half_rn(accR[mt][nt][3]);
            }
        }
}

// ---------------- fused edge kernel ------------------------------------------
// per tile: gather | GEMM1' | epi1 | {w0-3: GEMM2->mf->scatter  ||  w4-7:
// GEMM3 = e@We_e + hid@P -> e_new}.   GEMM3 no longer depends on m.
__global__ void __launch_bounds__(EK_THREADS, 1)
edge_kernel(const float* __restrict__ h, const float* __restrict__ e,
            const int* __restrict__ senders, const int* __restrict__ receivers,
            const float* __restrict__ W1, const float* __restrict__ b1,
            const float* __restrict__ W2, const float* __restrict__ b2,
            const float* __restrict__ We, const float* __restrict__ be,
            float* __restrict__ out_e)
{
    extern __shared__ char smc[];
    uint32_t* W1w  = (uint32_t*)(smc + OFF_W1E);
    uint32_t* W2w  = (uint32_t*)(smc + OFF_W2);
    uint32_t* WEew = (uint32_t*)(smc + OFF_WEE);
    uint32_t* Pw   = (uint32_t*)(smc + OFF_P);
    uint32_t* b1h  = (uint32_t*)(smc + OFF_BI1H);
    float* bi2  = (float*)(smc + OFF_BI2);
    float* bie2 = (float*)(smc + OFF_BIE2);

    const int tid = threadIdx.x;

    // ---- stage weights + biases ---------------------------------------------
    for (int i = tid; i < DH * 32; i += EK_THREADS) {         // W1e
        int c = i >> 5, k2 = i & 31;
        W1w[c * 36 + k2] = packh2(W1[(2 * k2) * DH + c], W1[(2 * k2 + 1) * DH + c]);
    }
    for (int i = tid; i < D * (DH / 2); i += EK_THREADS) {    // W2
        int c = i >> 6, k2 = i & 63;
        W2w[c * 68 + k2] = packh2(W2[(2 * k2) * D + c], W2[(2 * k2 + 1) * D + c]);
    }
    for (int i = tid; i < D * 32; i += EK_THREADS) {          // We_e (K=64)
        int c = i >> 5, k2 = i & 31;
        WEew[c * 36 + k2] = packh2(We[(2 * k2) * D + c], We[(2 * k2 + 1) * D + c]);
    }
    for (int i = tid; i < D * (DH / 2); i += EK_THREADS) {    // P (fp16 source)
        int c = i >> 6, k2 = i & 63;
        __half2 h2 = __halves2half2(g_P[(2 * k2) * D + c], g_P[(2 * k2 + 1) * D + c]);
        Pw[c * 68 + k2] = *(uint32_t*)&h2;
    }
    if (tid < D) b1h[tid]  = packh2(b1[2 * tid], b1[2 * tid + 1]);
    if (tid < D) bi2[tid]  = b2[tid];
    if (tid < D) bie2[tid] = g_be2[tid];
    __syncthreads();

    // ---- group-local state ---------------------------------------------------
    const int gi   = tid >> 8;
    const int lt   = tid & 255;
    const int w    = lt >> 5;
    const int lane = lt & 31;
    const int g    = lane >> 2;
    const int tig  = lane & 3;

    char* gbase = smc + OFF_GRP + gi * GRP_BYTES;
    uint32_t* Xw   = (uint32_t*)gbase;
    __half*   Xh   = (__half*)gbase;
    uint32_t* HSRw = (uint32_t*)(gbase + GOFF_HSR);
    float*    mf   = (float*)(gbase + GOFF_HSR);   // overlays HSR (time-disjoint)
    int*      ridx = (int*)(gbase + GOFF_RIDX);

    const uint32_t Xs   = (uint32_t)__cvta_generic_to_shared(Xw);
    const uint32_t W1s  = (uint32_t)__cvta_generic_to_shared(W1w);
    const uint32_t W2s  = (uint32_t)__cvta_generic_to_shared(W2w);
    const uint32_t WEes = (uint32_t)__cvta_generic_to_shared(WEew);
    const uint32_t Ps   = (uint32_t)__cvta_generic_to_shared(Pw);

    const int c0w1 = (w & 3) * 32;
    const int e0w1 = (w >> 2) * 32;
    const int wl   = w & 3;
    const int c0w2 = (wl & 1) * 32;
    const int e0w2 = (wl >> 1) * 32;
    const int barid  = gi + 1;       // group-wide (256)
    const int barid2 = gi + 3;       // w0-3 half-group (128)

    // ldmatrix lane-address components
    const int rA  = (lane & 7) + ((lane >> 3) & 1) * 8;
    const int cA4 = (lane >> 4) << 2;
    const int rB  = (lane & 7) + ((lane >> 4) << 3);
    const int cB4 = ((lane >> 3) & 1) << 2;

    const uint32_t aW1b  = W1s  + ((c0w1 + rA) * 36 + cA4) * 4;   // +2304/mt
    const uint32_t aW2b  = W2s  + ((c0w2 + rA) * 68 + cA4) * 4;   // +4352/mt
    const uint32_t aWEeb = WEes + ((c0w2 + rA) * 36 + cA4) * 4;   // +2304/mt
    const uint32_t aPb   = Ps   + ((c0w2 + rA) * 68 + cA4) * 4;   // +4352/mt
    const uint32_t bX1b  = Xs + ((e0w1 + rB) * XSTRW + cB4) * 4;  // +6400/np
    const uint32_t bX2b  = Xs + ((e0w2 + rB) * XSTRW + cB4) * 4;

    #define BARG() asm volatile("bar.sync %0, 256;" :: "r"(barid) : "memory")

    for (int tile = blockIdx.x * 2 + gi; tile < N_TILES; tile += 2 * gridDim.x) {
        const int base = tile * TILE_E;
        BARG();   // S0: prev scatter + GEMM3 done; X/HSR/mf/ridx reusable

        // ====== gather: e -> X rows (fp16), H1[s]+H2[r]+b1 -> HSR pairs ======
        {
            const int el = lt & 63;
            const int p4 = lt >> 6;
            const int sI = senders[base + el];
            const int rI = receivers[base + el];
            if (p4 == 0) ridx[el] = rI;

            const float4* ep = (const float4*)(e + (size_t)(base + el) * D) + p4 * 4;
            uint32_t ew[8];
            #pragma unroll
            for (int q = 0; q < 4; q++) {
                float4 v = ep[q];
                ew[2 * q]     = packh2(v.x, v.y);
                ew[2 * q + 1] = packh2(v.z, v.w);
            }
            uint4* xdst = (uint4*)(Xw + el * XSTRW + p4 * 8);
            xdst[0] = make_uint4(ew[0], ew[1], ew[2], ew[3]);
            xdst[1] = make_uint4(ew[4], ew[5], ew[6], ew[7]);

            const uint4* h1p = (const uint4*)(g_H1 + (size_t)sI * DH) + p4 * 4;
            const uint4* h2p = (const uint4*)(g_H2 + (size_t)rI * DH) + p4 * 4;
            uint32_t hw[16];
            #pragma unroll
            for (int q = 0; q < 4; q++) {
                uint4 a = h1p[q], b = h2p[q];
                const __half2* bb = (const __half2*)(b1h + (p4 * 4 + q) * 4);
                __half2 s0 = __hadd2(__hadd2(*(__half2*)&a.x, *(__half2*)&b.x), bb[0]);
                __half2 s1 = __hadd2(__hadd2(*(__half2*)&a.y, *(__half2*)&b.y), bb[1]);
                __half2 s2 = __hadd2(__hadd2(*(__half2*)&a.z, *(__half2*)&b.z), bb[2]);
                __half2 s3 = __hadd2(__hadd2(*(__half2*)&a.w, *(__half2*)&b.w), bb[3]);
                hw[q * 4 + 0] = *(uint32_t*)&s0;
                hw[q * 4 + 1] = *(uint32_t*)&s1;
                hw[q * 4 + 2] = *(uint32_t*)&s2;
                hw[q * 4 + 3] = *(uint32_t*)&s3;
            }
            uint32_t pw[16];
            #pragma unroll
            for (int bq = 0; bq < 2; bq++) {
                const __half2* s0 = (const __half2*)(hw + bq * 8);
                const __half2* s1 = (const __half2*)(hw + bq * 8 + 4);
                #pragma unroll
                for (int j = 0; j < 4; j++) {
                    __half2 lo = __lows2half2(s0[j], s1[j]);
                    __half2 hi = __highs2half2(s0[j], s1[j]);
                    pw[bq * 8 + 2 * j]     = *(uint32_t*)&lo;
                    pw[bq * 8 + 2 * j + 1] = *(uint32_t*)&hi;
                }
            }
            uint4* hdst = (uint4*)(HSRw + el * HSTRW + p4 * 16);
            hdst[0] = make_uint4(pw[0],  pw[1],  pw[2],  pw[3]);
            hdst[1] = make_uint4(pw[4],  pw[5],  pw[6],  pw[7]);
            hdst[2] = make_uint4(pw[8],  pw[9],  pw[10], pw[11]);
            hdst[3] = make_uint4(pw[12], pw[13], pw[14], pw[15]);
        }
        BARG();   // S1

        // ====== GEMM1': acc init = HSR(+b1); += e @ W1e (K=64) ===============
        float acc1[2][4][4];
        {
            const int cpb = 16 * (w & 3);
            #pragma unroll
            for (int mt = 0; mt < 2; mt++)
                #pragma unroll
                for (int nt = 0; nt < 4; nt++) {
                    int eA = e0w1 + 8 * nt + 2 * tig;
                    int cp = cpb + 8 * mt + g;
                    uint32_t v0 = HSRw[eA * HSTRW + cp];
                    uint32_t v1 = HSRw[(eA + 1) * HSTRW + cp];
                    float2 f0 = __half22float2(*(__half2*)&v0);
                    float2 f1 = __half22float2(*(__half2*)&v1);
                    acc1[mt][nt][0] = f0.x; acc1[mt][nt][2] = f0.y;
                    acc1[mt][nt][1] = f1.x; acc1[mt][nt][3] = f1.y;
                }
        }
        #pragma unroll
        for (int kt = 0; kt < 4; kt++) {
            uint32_t av[2][4], bv[2][4];
            ldsm4(av[0], aW1b + kt * 32);
            ldsm4(av[1], aW1b + 2304 + kt * 32);
            ldsm4(bv[0], bX1b + kt * 32);
            ldsm4(bv[1], bX1b + 6400 + kt * 32);
            #pragma unroll
            for (int mt = 0; mt < 2; mt++)
                #pragma unroll
                for (int np = 0; np < 2; np++) {
                    mma16(acc1[mt][2 * np],     av[mt], bv[np]);
                    mma16(acc1[mt][2 * np + 1], av[mt], bv[np] + 2);
                }
        }
        BARG();   // S2

        // ===== epilogue1: hid = relu(acc) -> X halves 64+c ===================
        #pragma unroll
        for (int mt = 0; mt < 2; mt++)
            #pragma unroll
            for (int nt = 0; nt < 4; nt++) {
                int cA = c0w1 + 16 * mt + g;
                int eA = e0w1 + 8 * nt + 2 * tig;
                Xh[eA * 200 + 64 + cA]           = __float2half_rn(fmaxf(acc1[mt][nt][0], 0.f));
                Xh[(eA + 1) * 200 + 64 + cA]     = __float2half_rn(fmaxf(acc1[mt][nt][1], 0.f));
                Xh[eA * 200 + 64 + cA + 8]       = __float2half_rn(fmaxf(acc1[mt][nt][2], 0.f));
                Xh[(eA + 1) * 200 + 64 + cA + 8] = __float2half_rn(fmaxf(acc1[mt][nt][3], 0.f));
            }
        BARG();   // S3

        float acc2[2][4][4];
        #pragma unroll
        for (int mt = 0; mt < 2; mt++)
            #pragma unroll
            for (int nt = 0; nt < 4; nt++)
                #pragma unroll
                for (int q = 0; q < 4; q++) acc2[mt][nt][q] = 0.f;

        if (w < 4) {
            // ===== GEMM2: m = hid @ W2 (K=128) -> mf -> scatter ==============
            #pragma unroll
            for (int kt = 0; kt < 8; kt++) {
                uint32_t av[2][4], bv[2][4];
                ldsm4(av[0], aW2b + kt * 32);
                ldsm4(av[1], aW2b + 4352 + kt * 32);
                ldsm4(bv[0], bX2b + 128 + kt * 32);
                ldsm4(bv[1], bX2b + 6400 + 128 + kt * 32);
                #pragma unroll
                for (int mt = 0; mt < 2; mt++)
                    #pragma unroll
                    for (int np = 0; np < 2; np++) {
                        mma16(acc2[mt][2 * np],     av[mt], bv[np]);
                        mma16(acc2[mt][2 * np + 1], av[mt], bv[np] + 2);
                    }
            }
            #pragma unroll
            for (int mt = 0; mt < 2; mt++)
                #pragma unroll
                for (int nt = 0; nt < 4; nt++) {
                    int cA = c0w2 + 16 * mt + g;
                    int eA = e0w2 + 8 * nt + 2 * tig;
                    mf[eA * HSTRW + cA]           = acc2[mt][nt][0] + bi2[cA];
                    mf[(eA + 1) * HSTRW + cA]     = acc2[mt][nt][1] + bi2[cA];
                    mf[eA * HSTRW + cA + 8]       = acc2[mt][nt][2] + bi2[cA + 8];
                    mf[(eA + 1) * HSTRW + cA + 8] = acc2[mt][nt][3] + bi2[cA + 8];
                }
            asm volatile("bar.sync %0, 128;" :: "r"(barid2) : "memory");
            // scatter: red.global.add.v4.f32
            const int el = lt & 63;
            const int hf = (lt >> 6) & 1;
            const int r  = ridx[el];
            const float4* mrow4 = (const float4*)(mf + el * HSTRW + hf * 32);
            float* dstp = g_agg + (size_t)r * D + hf * 32;
            #pragma unroll
            for (int c4 = 0; c4 < 8; c4++)
                red4(dstp + c4 * 4, mrow4[c4]);
        } else {
            // ===== GEMM3: e @ We_e (K=64) + hid @ P (K=128) -> e_new =========
            #pragma unroll
            for (int kt = 0; kt < 4; kt++) {
                uint32_t av[2][4], bv[2][4];
                ldsm4(av[0], aWEeb + kt * 32);
                ldsm4(av[1], aWEeb + 2304 + kt * 32);
                ldsm4(bv[0], bX2b + kt * 32);
                ldsm4(bv[1], bX2b + 6400 + kt * 32);
                #pragma unroll
                for (int mt = 0; mt < 2; mt++)
                    #pragma unroll
                    for (int np = 0; np < 2; np++) {
                        mma16(acc2[mt][2 * np],     av[mt], bv[np]);
                        mma16(acc2[mt][2 * np + 1], av[mt], bv[np] + 2);
                    }
            }
            #pragma unroll
            for (int kt = 0; kt < 8; kt++) {
                uint32_t av[2][4], bv[2][4];
                ldsm4(av[0], aPb + kt * 32);
                ldsm4(av[1], aPb + 4352 + kt * 32);
                ldsm4(bv[0], bX2b + 128 + kt * 32);
                ldsm4(bv[1], bX2b + 6400 + 128 + kt * 32);
                #pragma unroll
                for (int mt = 0; mt < 2; mt++)
                    #pragma unroll
                    for (int np = 0; np < 2; np++) {
                        mma16(acc2[mt][2 * np],     av[mt], bv[np]);
                        mma16(acc2[mt][2 * np + 1], av[mt], bv[np] + 2);
                    }
            }
            // epilogue: e_new = relu(acc + be') -> gmem
            #pragma unroll
            for (int mt = 0; mt < 2; mt++)
                #pragma unroll
                for (int nt = 0; nt < 4; nt++) {
                    int cA = c0w2 + 16 * mt + g;
                    int eA = e0w2 + 8 * nt + 2 * tig;
                    float* d0 = out_e + (size_t)(base + eA) * D;
                    float* d1 = out_e + (size_t)(base + eA + 1) * D;
                    d0[cA]     = fmaxf(acc2[mt][nt][0] + bie2[cA], 0.f);
                    d1[cA]     = fmaxf(acc2[mt][nt][1] + bie2[cA], 0.f);
                    d0[cA + 8] = fmaxf(acc2[mt][nt][2] + bie2[cA + 8], 0.f);
                    d1[cA + 8] = fmaxf(acc2[mt][nt][3] + bie2[cA + 8], 0.f);
                }
        }
    }
    #undef BARG
}

// ---------------- node kernel: h_new = relu([h | agg] @ W_node + b) ----------
#define NT    32
#define NPAD  36
#define NOFF_W 0
#define NOFF_B (NOFF_W + DH * D)
#define NOFF_X (NOFF_B + D)
#define SMEM_NODE_FLOATS (NOFF_X + DH * NPAD)
#define SMEM_NODE_BYTES  (SMEM_NODE_FLOATS * 4)

__global__ void __launch_bounds__(128)
node_kernel(const float* __restrict__ h,
            const float* __restrict__ Wn, const float* __restrict__ bn,
            float* __restrict__ out_h)
{
    extern __shared__ float sm[];
    const int tid = threadIdx.x;

    for (int i = tid; i < DH * D / 4; i += 128)
        ((float4*)(sm + NOFF_W))[i] = ((const float4*)Wn)[i];
    if (tid < D) sm[NOFF_B + tid] = bn[tid];
    __syncthreads();

    const int nl   = tid >> 2;
    const int part = tid & 3;
    const int ng   = tid >> 4;
    const int cgc  = tid & 15;

    const int n_tiles = N_NODES / NT;
    for (int tile = blockIdx.x; tile < n_tiles; tile += gridDim.x) {
        const int base = tile * NT;
        {
            const float4* hp = (const float4*)(h + (size_t)(base + nl) * D) + part * 4;
            const float4* ap = (const float4*)(g_agg + (size_t)(base + nl) * D) + part * 4;
            #pragma unroll
            for (int q = 0; q < 4; q++) {
                float4 v = hp[q];
                int k0 = part * 16 + q * 4;
                sm[NOFF_X + (k0 + 0) * NPAD + nl] = v.x;
                sm[NOFF_X + (k0 + 1) * NPAD + nl] = v.y;
                sm[NOFF_X + (k0 + 2) * NPAD + nl] = v.z;
                sm[NOFF_X + (k0 + 3) * NPAD + nl] = v.w;
            }
            #pragma unroll
            for (int q = 0; q < 4; q++) {
                float4 v = ap[q];
                int k0 = 64 + part * 16 + q * 4;
                sm[NOFF_X + (k0 + 0) * NPAD + nl] = v.x;
                sm[NOFF_X + (k0 + 1) * NPAD + nl] = v.y;
                sm[NOFF_X + (k0 + 2) * NPAD + nl] = v.z;
                sm[NOFF_X + (k0 + 3) * NPAD + nl] = v.w;
            }
        }
        __syncthreads();

        float acc[4][4];
        #pragma unroll
        for (int i = 0; i < 4; i++)
            #pragma unroll
            for (int j = 0; j < 4; j++) acc[i][j] = 0.f;

        const float* Xb = sm + NOFF_X + ng * 4;
        const float* Wb = sm + NOFF_W + cgc * 4;
        #pragma unroll 4
        for (int k = 0; k < DH; k++) {
            float4 a = *(const float4*)(Xb + k * NPAD);
            float4 wv4 = *(const float4*)(Wb + k * D);
            float av[4] = {a.x, a.y, a.z, a.w};
            float wv[4] = {wv4.x, wv4.y, wv4.z, wv4.w};
            #pragma unroll
            for (int i = 0; i < 4; i++)
                #pragma unroll
                for (int j = 0; j < 4; j++)
                    acc[i][j] = fmaf(av[i], wv[j], acc[i][j]);
        }
        float bb[4];
        #pragma unroll
        for (int j = 0; j < 4; j++) bb[j] = sm[NOFF_B + cgc * 4 + j];
        #pragma unroll
        for (int i = 0; i < 4; i++) {
            float4 v;
            v.x = fmaxf(acc[i][0] + bb[0], 0.f);
            v.y = fmaxf(acc[i][1] + bb[1], 0.f);
            v.z = fmaxf(acc[i][2] + bb[2], 0.f);
            v.w = fmaxf(acc[i][3] + bb[3], 0.f);
            *(float4*)(out_h + (size_t)(base + ng * 4 + i) * D + cgc * 4) = v;
        }
        __syncthreads();
    }
}

// ---------------- launch -----------------------------------------------------
extern "C" void kernel_launch(void* const* d_in, const int* in_sizes, int n_in,
                              void* d_out, int out_size)
{
    const float* h        = (const float*)d_in[0];
    const float* e        = (const float*)d_in[1];
    const int*   senders  = (const int*)d_in[2];
    const int*   receivers= (const int*)d_in[3];
    const float* W1       = (const float*)d_in[4];
    const float* b1       = (const float*)d_in[5];
    const float* W2       = (const float*)d_in[6];
    const float* b2       = (const float*)d_in[7];
    const float* Wn       = (const float*)d_in[8];
    const float* bn       = (const float*)d_in[9];
    const float* We       = (const float*)d_in[10];
    const float* be       = (const float*)d_in[11];

    float* out_h = (float*)d_out;
    float* out_e = out_h + (size_t)N_NODES * D;

    cudaFuncSetAttribute(edge_kernel, cudaFuncAttributeMaxDynamicSharedMemorySize,
                         SMEM_EDGE_BYTES);
    cudaFuncSetAttribute(node_kernel, cudaFuncAttributeMaxDynamicSharedMemorySize,
                         SMEM_NODE_BYTES);

    zero_agg_kernel<<<(N_NODES * D / 4 + 255) / 256, 256>>>();
    pw_kernel<<<(DH * D + 255) / 256, 256>>>(W2, We, b2, be);
    pre_kernel<<<(N_NODES + 63) / 64, 256, SMEM_PRE_BYTES>>>(h, W1);
    edge_kernel<<<EK_GRID, EK_THREADS, SMEM_EDGE_BYTES>>>(
        h, e, senders, receivers, W1, b1, W2, b2, We, be, out_e);
    node_kernel<<<1480, 128, SMEM_NODE_BYTES>>>(h, Wn, bn, out_h);
}

// round 14
// speedup vs baseline: 1.5986x; 1.1608x over previous
#include <cuda_runtime.h>
#include <cuda_fp16.h>
#include <cstdint>

#define N_NODES 100000
#define N_EDGES 1600000
#define D       64
#define DH      128
#define KIN     192

#define TILE_E   64
#define N_TILES  (N_EDGES / TILE_E)   // 25000
#define EK_GRID  148
#define EK_THREADS 512                // 2 groups x 256

// ---------------- edge-kernel smem byte offsets ------------------------------
#define OFF_W1E   0          // W1e^T fp16 [128 rows][36 w] = 18432
#define OFF_W2    18432      // W2^T [64 rows][68 w] = 17408
#define OFF_WEE   35840      // We_e^T (K=64) [64 rows][36 w] = 9216
#define OFF_P     45056      // P^T = (W2@We_m)^T [64 rows][68 w] = 17408
#define OFF_BI1H  62464      // b1 half2 = 256
#define OFF_BI2   62720      // b2 fp32 = 256
#define OFF_BIE2  62976      // be' fp32 = 256
#define OFF_GRP   63232
// group block: X 64x100 words 25600 | HSR/mf (overlaid) 64x68 words 17408 | ridx 256
#define GRP_BYTES 43264
#define GOFF_HSR  25600
#define GOFF_RIDX 43008
#define SMEM_EDGE_BYTES (OFF_GRP + 2 * GRP_BYTES)   // 149760

#define XSTRW 100            // X row stride in words
#define HSTRW 68             // HSR/mf row stride in words

// ---------------- precompute-kernel smem -------------------------------------
#define POFF_WS   0
#define POFF_WR   18432
#define POFF_PL   36864
#define SMEM_PRE_BYTES 45056

// ---------------- helpers ----------------------------------------------------
__device__ __forceinline__ uint32_t packh2(float lo, float hi) {
    uint32_t d;
    asm("cvt.rn.f16x2.f32 %0, %1, %2;" : "=r"(d) : "f"(hi), "f"(lo));
    return d;
}
__device__ __forceinline__ void mma16(float* c, const uint32_t* a, const uint32_t* b) {
    asm volatile(
        "mma.sync.aligned.m16n8k16.row.col.f32.f16.f16.f32 "
        "{%0,%1,%2,%3}, {%4,%5,%6,%7}, {%8,%9}, {%0,%1,%2,%3};"
        : "+f"(c[0]), "+f"(c[1]), "+f"(c[2]), "+f"(c[3])
        : "r"(a[0]), "r"(a[1]), "r"(a[2]), "r"(a[3]), "r"(b[0]), "r"(b[1]));
}
__device__ __forceinline__ void ldsm4(uint32_t* r, uint32_t saddr) {
    asm volatile("ldmatrix.sync.aligned.m8n8.x4.shared.b16 {%0,%1,%2,%3}, [%4];"
        : "=r"(r[0]), "=r"(r[1]), "=r"(r[2]), "=r"(r[3]) : "r"(saddr));
}
__device__ __forceinline__ void red4(float* p, float4 v) {
    asm volatile("red.global.add.v4.f32 [%0], {%1,%2,%3,%4};"
        :: "l"(p), "f"(v.x), "f"(v.y), "f"(v.z), "f"(v.w) : "memory");
}

// ---------------- scratch ----------------------------------------------------
__device__ float  g_agg[(size_t)N_NODES * D];
__device__ __half g_H1[(size_t)N_NODES * DH];
__device__ __half g_H2[(size_t)N_NODES * DH];
__device__ __half g_P[DH * D];      // W2 @ We_m  (fp16)
__device__ float  g_be2[D];         // b2 @ We_m + be

__global__ void zero_agg_kernel() {
    size_t i = (size_t)blockIdx.x * blockDim.x + threadIdx.x;
    size_t n4 = (size_t)N_NODES * D / 4;
    if (i < n4) ((float4*)g_agg)[i] = make_float4(0.f, 0.f, 0.f, 0.f);
}

// ---------------- tiny: P = W2 @ We_m,  be' = b2 @ We_m + be -----------------
__global__ void __launch_bounds__(256)
pw_kernel(const float* __restrict__ W2, const float* __restrict__ We,
          const float* __restrict__ b2, const float* __restrict__ be)
{
    int i = blockIdx.x * 256 + threadIdx.x;
    if (i < DH * D) {
        int k = i / D, c = i % D;
        float s = 0.f;
        #pragma unroll 8
        for (int l = 0; l < D; l++)
            s += W2[k * D + l] * We[(D + l) * D + c];
        g_P[k * D + c] = __float2half_rn(s);
    }
    if (i < D) {
        float s = be[i];
        #pragma unroll 8
        for (int l = 0; l < D; l++)
            s += b2[l] * We[(D + l) * D + i];
        g_be2[i] = s;
    }
}

// ---------------- precompute: H1 = h@W1s, H2 = h@W1r -------------------------
__global__ void __launch_bounds__(256)
pre_kernel(const float* __restrict__ h, const float* __restrict__ W1)
{
    extern __shared__ char smc[];
    uint32_t* WSw = (uint32_t*)(smc + POFF_WS);
    uint32_t* WRw = (uint32_t*)(smc + POFF_WR);
    uint32_t* PW  = (uint32_t*)(smc + POFF_PL);

    const int tid  = threadIdx.x;
    const int w    = tid >> 5;
    const int lane = tid & 31;
    const int g    = lane >> 2;
    const int tig  = lane & 3;
    const int swz  = tig << 3;

    for (int i = tid; i < DH * 32; i += 256) {
        int c = i >> 5, k2 = i & 31;
        WSw[c * 36 + k2] = packh2(W1[(64 + 2 * k2) * DH + c],
                                  W1[(64 + 2 * k2 + 1) * DH + c]);
        WRw[c * 36 + k2] = packh2(W1[(128 + 2 * k2) * DH + c],
                                  W1[(128 + 2 * k2 + 1) * DH + c]);
    }
    __syncthreads();

    const int base = blockIdx.x * 64;
    {
        const int nl = tid & 63;
        const int p4 = tid >> 6;
        const int node = base + nl;
        #pragma unroll
        for (int q = 0; q < 4; q++) {
            float4 v = (node < N_NODES)
                ? ((const float4*)(h + (size_t)node * D))[p4 * 4 + q]
                : make_float4(0.f, 0.f, 0.f, 0.f);
            int p = p4 * 8 + q * 2;
            PW[p * 64 + (nl ^ ((p & 3) << 3))]             = packh2(v.x, v.y);
            PW[(p + 1) * 64 + (nl ^ (((p + 1) & 3) << 3))] = packh2(v.z, v.w);
        }
    }
    __syncthreads();

    const int c0 = (w & 3) * 32;
    const int n0 = (w >> 2) * 32;

    float accS[2][4][4], accR[2][4][4];
    #pragma unroll
    for (int mt = 0; mt < 2; mt++)
        #pragma unroll
        for (int nt = 0; nt < 4; nt++)
            #pragma unroll
            for (int q = 0; q < 4; q++) { accS[mt][nt][q] = 0.f; accR[mt][nt][q] = 0.f; }

    #pragma unroll
    for (int kt = 0; kt < 4; kt++) {
        const int k8 = kt * 8;
        uint32_t as[2][4], ar[2][4];
        #pragma unroll
        for (int mt = 0; mt < 2; mt++) {
            int r = c0 + 16 * mt + g;
            as[mt][0] = WSw[r * 36 + k8 + tig];
            as[mt][1] = WSw[(r + 8) * 36 + k8 + tig];
            as[mt][2] = WSw[r * 36 + k8 + tig + 4];
            as[mt][3] = WSw[(r + 8) * 36 + k8 + tig + 4];
            ar[mt][0] = WRw[r * 36 + k8 + tig];
            ar[mt][1] = WRw[(r + 8) * 36 + k8 + tig];
            ar[mt][2] = WRw[r * 36 + k8 + tig + 4];
            ar[mt][3] = WRw[(r + 8) * 36 + k8 + tig + 4];
        }
        uint32_t bv[4][2];
        const int p0 = k8 + tig;
        #pragma unroll
        for (int nt = 0; nt < 4; nt++) {
            int es = (n0 + nt * 8 + g) ^ swz;
            bv[nt][0] = PW[p0 * 64 + es];
            bv[nt][1] = PW[(p0 + 4) * 64 + es];
        }
        #pragma unroll
        for (int mt = 0; mt < 2; mt++)
            #pragma unroll
            for (int nt = 0; nt < 4; nt++) {
                mma16(accS[mt][nt], as[mt], bv[nt]);
                mma16(accR[mt][nt], ar[mt], bv[nt]);
            }
    }

    #pragma unroll
    for (int mt = 0; mt < 2; mt++)
        #pragma unroll
        for (int nt = 0; nt < 4; nt++) {
            int cA = c0 + 16 * mt + g;
            int nA = n0 + 8 * nt + 2 * tig;
            int d0 = base + nA, d1 = base + nA + 1;
            if (d0 < N_NODES) {
                g_H1[(size_t)d0 * DH + cA]     = __float2half_rn(accS[mt][nt][0]);
                g_H1[(size_t)d0 * DH + cA + 8] = __float2half_rn(accS[mt][nt][2]);
                g_H2[(size_t)d0 * DH + cA]     = __float2half_rn(accR[mt][nt][0]);
                g_H2[(size_t)d0 * DH + cA + 8] = __float2half_rn(accR[mt][nt][2]);
            }
            if (d1 < N_NODES) {
                g_H1[(size_t)d1 * DH + cA]     = __float2half_rn(accS[mt][nt][1]);
                g_H1[(size_t)d1 * DH + cA + 8] = __float2half_rn(accS[mt][nt][3]);
                g_H2[(size_t)d1 * DH + cA]     = __float2half_rn(accR[mt][nt][1]);
                g_H2[(size_t)d1 * DH + cA + 8] = __float2half_rn(accR[mt][nt][3]);
            }
        }
}

// ---------------- fused edge kernel ------------------------------------------
__global__ void __launch_bounds__(EK_THREADS, 1)
edge_kernel(const float* __restrict__ h, const float* __restrict__ e,
            const int* __restrict__ senders, const int* __restrict__ receivers,
            const float* __restrict__ W1, const float* __restrict__ b1,
            const float* __restrict__ W2, const float* __restrict__ b2,
            const float* __restrict__ We, const float* __restrict__ be,
            float* __restrict__ out_e)
{
    extern __shared__ char smc[];
    uint32_t* W1w  = (uint32_t*)(smc + OFF_W1E);
    uint32_t* W2w  = (uint32_t*)(smc + OFF_W2);
    uint32_t* WEew = (uint32_t*)(smc + OFF_WEE);
    uint32_t* Pw   = (uint32_t*)(smc + OFF_P);
    uint32_t* b1h  = (uint32_t*)(smc + OFF_BI1H);
    float* bi2  = (float*)(smc + OFF_BI2);
    float* bie2 = (float*)(smc + OFF_BIE2);

    const int tid = threadIdx.x;

    // ---- stage weights + biases ---------------------------------------------
    for (int i = tid; i < DH * 32; i += EK_THREADS) {         // W1e
        int c = i >> 5, k2 = i & 31;
        W1w[c * 36 + k2] = packh2(W1[(2 * k2) * DH + c], W1[(2 * k2 + 1) * DH + c]);
    }
    for (int i = tid; i < D * (DH / 2); i += EK_THREADS) {    // W2
        int c = i >> 6, k2 = i & 63;
        W2w[c * 68 + k2] = packh2(W2[(2 * k2) * D + c], W2[(2 * k2 + 1) * D + c]);
    }
    for (int i = tid; i < D * 32; i += EK_THREADS) {          // We_e (K=64)
        int c = i >> 5, k2 = i & 31;
        WEew[c * 36 + k2] = packh2(We[(2 * k2) * D + c], We[(2 * k2 + 1) * D + c]);
    }
    for (int i = tid; i < D * (DH / 2); i += EK_THREADS) {    // P (fp16 source)
        int c = i >> 6, k2 = i & 63;
        __half2 h2 = __halves2half2(g_P[(2 * k2) * D + c], g_P[(2 * k2 + 1) * D + c]);
        Pw[c * 68 + k2] = *(uint32_t*)&h2;
    }
    if (tid < D) b1h[tid]  = packh2(b1[2 * tid], b1[2 * tid + 1]);
    if (tid < D) bi2[tid]  = b2[tid];
    if (tid < D) bie2[tid] = g_be2[tid];
    __syncthreads();

    // ---- group-local state ---------------------------------------------------
    const int gi   = tid >> 8;
    const int lt   = tid & 255;
    const int w    = lt >> 5;
    const int lane = lt & 31;
    const int g    = lane >> 2;
    const int tig  = lane & 3;

    char* gbase = smc + OFF_GRP + gi * GRP_BYTES;
    uint32_t* Xw   = (uint32_t*)gbase;
    __half*   Xh   = (__half*)gbase;
    uint32_t* HSRw = (uint32_t*)(gbase + GOFF_HSR);
    float*    mf   = (float*)(gbase + GOFF_HSR);   // overlays HSR (time-disjoint)
    int*      ridx = (int*)(gbase + GOFF_RIDX);

    const uint32_t Xs   = (uint32_t)__cvta_generic_to_shared(Xw);
    const uint32_t W1s  = (uint32_t)__cvta_generic_to_shared(W1w);
    const uint32_t W2s  = (uint32_t)__cvta_generic_to_shared(W2w);
    const uint32_t WEes = (uint32_t)__cvta_generic_to_shared(WEew);
    const uint32_t Ps   = (uint32_t)__cvta_generic_to_shared(Pw);

    const int c0w1 = (w & 3) * 32;
    const int e0w1 = (w >> 2) * 32;
    const int wl   = w & 3;
    const int c0w2 = (wl & 1) * 32;
    const int e0w2 = (wl >> 1) * 32;
    const int barid  = gi + 1;       // group-wide (256)
    const int barid2 = gi + 3;       // w0-3 half-group (128)

    // ldmatrix lane-address components
    const int rA  = (lane & 7) + ((lane >> 3) & 1) * 8;
    const int cA4 = (lane >> 4) << 2;
    const int rB  = (lane & 7) + ((lane >> 4) << 3);
    const int cB4 = ((lane >> 3) & 1) << 2;

    const uint32_t aW1b  = W1s  + ((c0w1 + rA) * 36 + cA4) * 4;
    const uint32_t aW2b  = W2s  + ((c0w2 + rA) * 68 + cA4) * 4;
    const uint32_t aWEeb = WEes + ((c0w2 + rA) * 36 + cA4) * 4;
    const uint32_t aPb   = Ps   + ((c0w2 + rA) * 68 + cA4) * 4;
    const uint32_t bX1b  = Xs + ((e0w1 + rB) * XSTRW + cB4) * 4;
    const uint32_t bX2b  = Xs + ((e0w2 + rB) * XSTRW + cB4) * 4;

    // gather lane maps
    const int el2 = lt >> 2;         // H gather: edge (4 lanes per edge)
    const int p4r = lt & 3;          // H gather: quarter

    #define BARG() asm volatile("bar.sync %0, 256;" :: "r"(barid) : "memory")

    for (int tile = blockIdx.x * 2 + gi; tile < N_TILES; tile += 2 * gridDim.x) {
        const int base = tile * TILE_E;
        BARG();   // S0: prev scatter + GEMM3 done; X/HSR/mf/ridx reusable

        // ====== gather (coalesced): e -> X rows; H1[s]+H2[r]+b1 -> HSR =======
        {
            // --- e: fully coalesced linear loads, scatter-store to X rows ----
            const float4* e4 = (const float4*)(e + (size_t)base * D);
            #pragma unroll
            for (int q = 0; q < 4; q++) {
                int gidx = lt + q * 256;             // 0..1023 float4s
                float4 v = e4[gidx];
                int ed = gidx >> 4, ch = gidx & 15;
                *(uint2*)(Xw + ed * XSTRW + ch * 2) =
                    make_uint2(packh2(v.x, v.y), packh2(v.z, v.w));
            }

            // --- H: 4 lanes per edge row (sector-efficient) ------------------
            const int sI = senders[base + el2];
            const int rI = receivers[base + el2];
            if (p4r == 0) ridx[el2] = rI;

            const uint4* h1p = (const uint4*)(g_H1 + (size_t)sI * DH) + p4r * 4;
            const uint4* h2p = (const uint4*)(g_H2 + (size_t)rI * DH) + p4r * 4;
            uint32_t hw[16];
            #pragma unroll
            for (int q = 0; q < 4; q++) {
                uint4 a = h1p[q], b = h2p[q];
                const __half2* bb = (const __half2*)(b1h + (p4r * 4 + q) * 4);
                __half2 s0 = __hadd2(__hadd2(*(__half2*)&a.x, *(__half2*)&b.x), bb[0]);
                __half2 s1 = __hadd2(__hadd2(*(__half2*)&a.y, *(__half2*)&b.y), bb[1]);
                __half2 s2 = __hadd2(__hadd2(*(__half2*)&a.z, *(__half2*)&b.z), bb[2]);
                __half2 s3 = __hadd2(__hadd2(*(__half2*)&a.w, *(__half2*)&b.w), bb[3]);
                hw[q * 4 + 0] = *(uint32_t*)&s0;
                hw[q * 4 + 1] = *(uint32_t*)&s1;
                hw[q * 4 + 2] = *(uint32_t*)&s2;
                hw[q * 4 + 3] = *(uint32_t*)&s3;
            }
            uint32_t pw[16];
            #pragma unroll
            for (int bq = 0; bq < 2; bq++) {
                const __half2* s0 = (const __half2*)(hw + bq * 8);
                const __half2* s1 = (const __half2*)(hw + bq * 8 + 4);
                #pragma unroll
                for (int j = 0; j < 4; j++) {
                    __half2 lo = __lows2half2(s0[j], s1[j]);
                    __half2 hi = __highs2half2(s0[j], s1[j]);
                    pw[bq * 8 + 2 * j]     = *(uint32_t*)&lo;
                    pw[bq * 8 + 2 * j + 1] = *(uint32_t*)&hi;
                }
            }
            uint4* hdst = (uint4*)(HSRw + el2 * HSTRW + p4r * 16);
            hdst[0] = make_uint4(pw[0],  pw[1],  pw[2],  pw[3]);
            hdst[1] = make_uint4(pw[4],  pw[5],  pw[6],  pw[7]);
            hdst[2] = make_uint4(pw[8],  pw[9],  pw[10], pw[11]);
            hdst[3] = make_uint4(pw[12], pw[13], pw[14], pw[15]);
        }
        BARG();   // S1

        // ====== GEMM1': acc init = HSR(+b1); += e @ W1e (K=64) ===============
        float acc1[2][4][4];
        {
            const int cpb = 16 * (w & 3);
            #pragma unroll
            for (int mt = 0; mt < 2; mt++)
                #pragma unroll
                for (int nt = 0; nt < 4; nt++) {
                    int eA = e0w1 + 8 * nt + 2 * tig;
                    int cp = cpb + 8 * mt + g;
                    uint32_t v0 = HSRw[eA * HSTRW + cp];
                    uint32_t v1 = HSRw[(eA + 1) * HSTRW + cp];
                    float2 f0 = __half22float2(*(__half2*)&v0);
                    float2 f1 = __half22float2(*(__half2*)&v1);
                    acc1[mt][nt][0] = f0.x; acc1[mt][nt][2] = f0.y;
                    acc1[mt][nt][1] = f1.x; acc1[mt][nt][3] = f1.y;
                }
        }
        #pragma unroll
        for (int kt = 0; kt < 4; kt++) {
            uint32_t av[2][4], bv[2][4];
            ldsm4(av[0], aW1b + kt * 32);
            ldsm4(av[1], aW1b + 2304 + kt * 32);
            ldsm4(bv[0], bX1b + kt * 32);
            ldsm4(bv[1], bX1b + 6400 + kt * 32);
            #pragma unroll
            for (int mt = 0; mt < 2; mt++)
                #pragma unroll
                for (int np = 0; np < 2; np++) {
                    mma16(acc1[mt][2 * np],     av[mt], bv[np]);
                    mma16(acc1[mt][2 * np + 1], av[mt], bv[np] + 2);
                }
        }
        BARG();   // S2

        // ===== epilogue1: hid = relu(acc) -> X halves 64+c ===================
        #pragma unroll
        for (int mt = 0; mt < 2; mt++)
            #pragma unroll
            for (int nt = 0; nt < 4; nt++) {
                int cA = c0w1 + 16 * mt + g;
                int eA = e0w1 + 8 * nt + 2 * tig;
                Xh[eA * 200 + 64 + cA]           = __float2half_rn(fmaxf(acc1[mt][nt][0], 0.f));
                Xh[(eA + 1) * 200 + 64 + cA]     = __float2half_rn(fmaxf(acc1[mt][nt][1], 0.f));
                Xh[eA * 200 + 64 + cA + 8]       = __float2half_rn(fmaxf(acc1[mt][nt][2], 0.f));
                Xh[(eA + 1) * 200 + 64 + cA + 8] = __float2half_rn(fmaxf(acc1[mt][nt][3], 0.f));
            }
        BARG();   // S3

        float acc2[2][4][4];
        #pragma unroll
        for (int mt = 0; mt < 2; mt++)
            #pragma unroll
            for (int nt = 0; nt < 4; nt++)
                #pragma unroll
                for (int q = 0; q < 4; q++) acc2[mt][nt][q] = 0.f;

        if (w < 4) {
            // ===== GEMM2: m = hid @ W2 (K=128) -> mf -> scatter ==============
            #pragma unroll
            for (int kt = 0; kt < 8; kt++) {
                uint32_t av[2][4], bv[2][4];
                ldsm4(av[0], aW2b + kt * 32);
                ldsm4(av[1], aW2b + 4352 + kt * 32);
                ldsm4(bv[0], bX2b + 128 + kt * 32);
                ldsm4(bv[1], bX2b + 6400 + 128 + kt * 32);
                #pragma unroll
                for (int mt = 0; mt < 2; mt++)
                    #pragma unroll
                    for (int np = 0; np < 2; np++) {
                        mma16(acc2[mt][2 * np],     av[mt], bv[np]);
                        mma16(acc2[mt][2 * np + 1], av[mt], bv[np] + 2);
                    }
            }
            #pragma unroll
            for (int mt = 0; mt < 2; mt++)
                #pragma unroll
                for (int nt = 0; nt < 4; nt++) {
                    int cA = c0w2 + 16 * mt + g;
                    int eA = e0w2 + 8 * nt + 2 * tig;
                    mf[eA * HSTRW + cA]           = acc2[mt][nt][0] + bi2[cA];
                    mf[(eA + 1) * HSTRW + cA]     = acc2[mt][nt][1] + bi2[cA];
                    mf[eA * HSTRW + cA + 8]       = acc2[mt][nt][2] + bi2[cA + 8];
                    mf[(eA + 1) * HSTRW + cA + 8] = acc2[mt][nt][3] + bi2[cA + 8];
                }
            asm volatile("bar.sync %0, 128;" :: "r"(barid2) : "memory");
            // scatter: red.global.add.v4.f32
            const int el = lt & 63;
            const int hf = (lt >> 6) & 1;
            const int r  = ridx[el];
            const float4* mrow4 = (const float4*)(mf + el * HSTRW + hf * 32);
            float* dstp = g_agg + (size_t)r * D + hf * 32;
            #pragma unroll
            for (int c4 = 0; c4 < 8; c4++)
                red4(dstp + c4 * 4, mrow4[c4]);
        } else {
            // ===== GEMM3: e @ We_e (K=64) + hid @ P (K=128) -> e_new =========
            #pragma unroll
            for (int kt = 0; kt < 4; kt++) {
                uint32_t av[2][4], bv[2][4];
                ldsm4(av[0], aWEeb + kt * 32);
                ldsm4(av[1], aWEeb + 2304 + kt * 32);
                ldsm4(bv[0], bX2b + kt * 32);
                ldsm4(bv[1], bX2b + 6400 + kt * 32);
                #pragma unroll
                for (int mt = 0; mt < 2; mt++)
                    #pragma unroll
                    for (int np = 0; np < 2; np++) {
                        mma16(acc2[mt][2 * np],     av[mt], bv[np]);
                        mma16(acc2[mt][2 * np + 1], av[mt], bv[np] + 2);
                    }
            }
            #pragma unroll
            for (int kt = 0; kt < 8; kt++) {
                uint32_t av[2][4], bv[2][4];
                ldsm4(av[0], aPb + kt * 32);
                ldsm4(av[1], aPb + 4352 + kt * 32);
                ldsm4(bv[0], bX2b + 128 + kt * 32);
                ldsm4(bv[1], bX2b + 6400 + 128 + kt * 32);
                #pragma unroll
                for (int mt = 0; mt < 2; mt++)
                    #pragma unroll
                    for (int np = 0; np < 2; np++) {
                        mma16(acc2[mt][2 * np],     av[mt], bv[np]);
                        mma16(acc2[mt][2 * np + 1], av[mt], bv[np] + 2);
                    }
            }
            // epilogue: e_new = relu(acc + be') -> gmem
            #pragma unroll
            for (int mt = 0; mt < 2; mt++)
                #pragma unroll
                for (int nt = 0; nt < 4; nt++) {
                    int cA = c0w2 + 16 * mt + g;
                    int eA = e0w2 + 8 * nt + 2 * tig;
                    float* d0 = out_e + (size_t)(base + eA) * D;
                    float* d1 = out_e + (size_t)(base + eA + 1) * D;
                    d0[cA]     = fmaxf(acc2[mt][nt][0] + bie2[cA], 0.f);
                    d1[cA]     = fmaxf(acc2[mt][nt][1] + bie2[cA], 0.f);
                    d0[cA + 8] = fmaxf(acc2[mt][nt][2] + bie2[cA + 8], 0.f);
                    d1[cA + 8] = fmaxf(acc2[mt][nt][3] + bie2[cA + 8], 0.f);
                }
        }
    }
    #undef BARG
}

// ---------------- node kernel: h_new = relu([h | agg] @ W_node + b) ----------
#define NT    32
#define NPAD  36
#define NOFF_W 0
#define NOFF_B (NOFF_W + DH * D)
#define NOFF_X (NOFF_B + D)
#define SMEM_NODE_FLOATS (NOFF_X + DH * NPAD)
#define SMEM_NODE_BYTES  (SMEM_NODE_FLOATS * 4)

__global__ void __launch_bounds__(128)
node_kernel(const float* __restrict__ h,
            const float* __restrict__ Wn, const float* __restrict__ bn,
            float* __restrict__ out_h)
{
    extern __shared__ float sm[];
    const int tid = threadIdx.x;

    for (int i = tid; i < DH * D / 4; i += 128)
        ((float4*)(sm + NOFF_W))[i] = ((const float4*)Wn)[i];
    if (tid < D) sm[NOFF_B + tid] = bn[tid];
    __syncthreads();

    const int nl   = tid >> 2;
    const int part = tid & 3;
    const int ng   = tid >> 4;
    const int cgc  = tid & 15;

    const int n_tiles = N_NODES / NT;
    for (int tile = blockIdx.x; tile < n_tiles; tile += gridDim.x) {
        const int base = tile * NT;
        {
            const float4* hp = (const float4*)(h + (size_t)(base + nl) * D) + part * 4;
            const float4* ap = (const float4*)(g_agg + (size_t)(base + nl) * D) + part * 4;
            #pragma unroll
            for (int q = 0; q < 4; q++) {
                float4 v = hp[q];
                int k0 = part * 16 + q * 4;
                sm[NOFF_X + (k0 + 0) * NPAD + nl] = v.x;
                sm[NOFF_X + (k0 + 1) * NPAD + nl] = v.y;
                sm[NOFF_X + (k0 + 2) * NPAD + nl] = v.z;
                sm[NOFF_X + (k0 + 3) * NPAD + nl] = v.w;
            }
            #pragma unroll
            for (int q = 0; q < 4; q++) {
                float4 v = ap[q];
                int k0 = 64 + part * 16 + q * 4;
                sm[NOFF_X + (k0 + 0) * NPAD + nl] = v.x;
                sm[NOFF_X + (k0 + 1) * NPAD + nl] = v.y;
                sm[NOFF_X + (k0 + 2) * NPAD + nl] = v.z;
                sm[NOFF_X + (k0 + 3) * NPAD + nl] = v.w;
            }
        }
        __syncthreads();

        float acc[4][4];
        #pragma unroll
        for (int i = 0; i < 4; i++)
            #pragma unroll
            for (int j = 0; j < 4; j++) acc[i][j] = 0.f;

        const float* Xb = sm + NOFF_X + ng * 4;
        const float* Wb = sm + NOFF_W + cgc * 4;
        #pragma unroll 4
        for (int k = 0; k < DH; k++) {
            float4 a = *(const float4*)(Xb + k * NPAD);
            float4 wv4 = *(const float4*)(Wb + k * D);
            float av[4] = {a.x, a.y, a.z, a.w};
            float wv[4] = {wv4.x, wv4.y, wv4.z, wv4.w};
            #pragma unroll
            for (int i = 0; i < 4; i++)
                #pragma unroll
                for (int j = 0; j < 4; j++)
                    acc[i][j] = fmaf(av[i], wv[j], acc[i][j]);
        }
        float bb[4];
        #pragma unroll
        for (int j = 0; j < 4; j++) bb[j] = sm[NOFF_B + cgc * 4 + j];
        #pragma unroll
        for (int i = 0; i < 4; i++) {
            float4 v;
            v.x = fmaxf(acc[i][0] + bb[0], 0.f);
            v.y = fmaxf(acc[i][1] + bb[1], 0.f);
            v.z = fmaxf(acc[i][2] + bb[2], 0.f);
            v.w = fmaxf(acc[i][3] + bb[3], 0.f);
            *(float4*)(out_h + (size_t)(base + ng * 4 + i) * D + cgc * 4) = v;
        }
        __syncthreads();
    }
}

// ---------------- launch -----------------------------------------------------
extern "C" void kernel_launch(void* const* d_in, const int* in_sizes, int n_in,
                              void* d_out, int out_size)
{
    const float* h        = (const float*)d_in[0];
    const float* e        = (const float*)d_in[1];
    const int*   senders  = (const int*)d_in[2];
    const int*   receivers= (const int*)d_in[3];
    const float* W1       = (const float*)d_in[4];
    const float* b1       = (const float*)d_in[5];
    const float* W2       = (const float*)d_in[6];
    const float* b2       = (const float*)d_in[7];
    const float* Wn       = (const float*)d_in[8];
    const float* bn       = (const float*)d_in[9];
    const float* We       = (const float*)d_in[10];
    const float* be       = (const float*)d_in[11];

    float* out_h = (float*)d_out;
    float* out_e = out_h + (size_t)N_NODES * D;

    cudaFuncSetAttribute(edge_kernel, cudaFuncAttributeMaxDynamicSharedMemorySize,
                         SMEM_EDGE_BYTES);
    cudaFuncSetAttribute(node_kernel, cudaFuncAttributeMaxDynamicSharedMemorySize,
                         SMEM_NODE_BYTES);

    zero_agg_kernel<<<(N_NODES * D / 4 + 255) / 256, 256>>>();
    pw_kernel<<<(DH * D + 255) / 256, 256>>>(W2, We, b2, be);
    pre_kernel<<<(N_NODES + 63) / 64, 256, SMEM_PRE_BYTES>>>(h, W1);
    edge_kernel<<<EK_GRID, EK_THREADS, SMEM_EDGE_BYTES>>>(
        h, e, senders, receivers, W1, b1, W2, b2, We, be, out_e);
    node_kernel<<<1480, 128, SMEM_NODE_BYTES>>>(h, Wn, bn, out_h);
}